// round 3
// baseline (speedup 1.0000x reference)
#include <cuda_runtime.h>
#include <cuda_bf16.h>
#include <cstdint>

// ---------------- problem constants ----------------
#define NN 40000      // nodes
#define EE 640000     // edges
#define CD 128        // channels (= IN = H*D)
#define HH 8          // heads
#define DD 16         // dim per head
#define EDD 64        // edge feature dim
#define C2 256        // FFN hidden
#define EPS 1e-5f

// ---------------- scratch (static device globals; no allocs allowed) ----------------
__device__ float    g_qd[(size_t)NN * CD];
__device__ float    g_kd[(size_t)NN * CD];
__device__ float    g_vd[(size_t)NN * CD];
__device__ float    g_eb[(size_t)EE * HH];    // per-edge bias
__device__ float    g_sc[(size_t)EE * HH];    // raw scores
__device__ unsigned g_smax[(size_t)NN * HH];  // ordered-uint encoded max
__device__ float    g_den[(size_t)NN * HH];
__device__ float    g_agg[(size_t)NN * CD];
__device__ float    g_rst[(size_t)NN * CD];
__device__ float    g_h1[(size_t)NN * C2];
__device__ float    g_h2[(size_t)NN * CD];
__device__ float    g_stats[4 * CD];          // [sum1, sq1, sum2, sq2]

// ---------------- helpers ----------------
__device__ __forceinline__ unsigned ordEnc(float f) {
    unsigned b = __float_as_uint(f);
    return (b & 0x80000000u) ? ~b : (b | 0x80000000u);
}
__device__ __forceinline__ float ordDec(unsigned u) {
    unsigned b = (u & 0x80000000u) ? (u ^ 0x80000000u) : ~u;
    return __uint_as_float(b);
}

// ---------------- init: zero accumulators every call (graph replays!) ----------------
__global__ void init_kernel() {
    int i = blockIdx.x * blockDim.x + threadIdx.x;
    int stride = gridDim.x * blockDim.x;
    for (int j = i; j < NN * CD; j += stride) g_agg[j] = 0.f;
    for (int j = i; j < NN * HH; j += stride) {
        g_den[j] = 0.f;
        g_smax[j] = 0x007FFFFFu;  // ordEnc(-inf)
    }
    if (i < 4 * CD) g_stats[i] = 0.f;
}

// ---------------- SGEMM: Y[M,Co] = X[M,K] @ W[Co,K]^T (+bias)(relu)(+res) ----------------
// BM=BN=128, BK=8, 256 threads, 8x8 microtile, double-buffered smem.
template <bool RELU, bool BIAS, bool RES>
__global__ void __launch_bounds__(256, 2)
sgemm_kernel(const float* __restrict__ X, const float* __restrict__ W,
             const float* __restrict__ bias, const float* __restrict__ res,
             float* __restrict__ Y, int M, int K, int Co) {
    __shared__ float Xs[2][8][132];
    __shared__ float Ws[2][8][132];
    const int t = threadIdx.x;
    const int tx = t & 15;         // 0..15 -> cols tx*8..+7
    const int ty = t >> 4;         // 0..15 -> rows ty*8..+7
    const int bm = blockIdx.x * 128;
    const int bn = blockIdx.y * 128;
    const int lrow = t >> 1;       // 0..127
    const int lk = (t & 1) * 4;    // 0 or 4

    const int xrow = min(bm + lrow, M - 1);   // clamp (tail block), safe dup read
    const float* Xg = X + (size_t)xrow * K + lk;
    const float* Wg = W + (size_t)(bn + lrow) * K + lk;

    float4 xv = *(const float4*)(Xg);
    float4 wv = *(const float4*)(Wg);
    Xs[0][lk + 0][lrow] = xv.x; Xs[0][lk + 1][lrow] = xv.y;
    Xs[0][lk + 2][lrow] = xv.z; Xs[0][lk + 3][lrow] = xv.w;
    Ws[0][lk + 0][lrow] = wv.x; Ws[0][lk + 1][lrow] = wv.y;
    Ws[0][lk + 2][lrow] = wv.z; Ws[0][lk + 3][lrow] = wv.w;
    __syncthreads();

    float acc[8][8] = {};
    int buf = 0;
    for (int k0 = 0; k0 < K; k0 += 8) {
        const bool more = (k0 + 8) < K;
        if (more) {
            xv = *(const float4*)(Xg + k0 + 8);
            wv = *(const float4*)(Wg + k0 + 8);
        }
#pragma unroll
        for (int k = 0; k < 8; k++) {
            float4 a0 = *(const float4*)&Xs[buf][k][ty * 8];
            float4 a1 = *(const float4*)&Xs[buf][k][ty * 8 + 4];
            float4 b0 = *(const float4*)&Ws[buf][k][tx * 8];
            float4 b1 = *(const float4*)&Ws[buf][k][tx * 8 + 4];
            float a_[8] = {a0.x, a0.y, a0.z, a0.w, a1.x, a1.y, a1.z, a1.w};
            float b_[8] = {b0.x, b0.y, b0.z, b0.w, b1.x, b1.y, b1.z, b1.w};
#pragma unroll
            for (int i = 0; i < 8; i++)
#pragma unroll
                for (int j = 0; j < 8; j++)
                    acc[i][j] += a_[i] * b_[j];
        }
        if (more) {
            const int nb = buf ^ 1;
            Xs[nb][lk + 0][lrow] = xv.x; Xs[nb][lk + 1][lrow] = xv.y;
            Xs[nb][lk + 2][lrow] = xv.z; Xs[nb][lk + 3][lrow] = xv.w;
            Ws[nb][lk + 0][lrow] = wv.x; Ws[nb][lk + 1][lrow] = wv.y;
            Ws[nb][lk + 2][lrow] = wv.z; Ws[nb][lk + 3][lrow] = wv.w;
            __syncthreads();
            buf = nb;
        }
    }

    const int n0 = bn + tx * 8;
    float4 bb0 = make_float4(0.f, 0.f, 0.f, 0.f);
    float4 bb1 = make_float4(0.f, 0.f, 0.f, 0.f);
    if (BIAS) {
        bb0 = *(const float4*)&bias[n0];
        bb1 = *(const float4*)&bias[n0 + 4];
    }
#pragma unroll
    for (int i = 0; i < 8; i++) {
        const int m = bm + ty * 8 + i;
        if (m < M) {
            float4 o0 = make_float4(acc[i][0], acc[i][1], acc[i][2], acc[i][3]);
            float4 o1 = make_float4(acc[i][4], acc[i][5], acc[i][6], acc[i][7]);
            if (BIAS) {
                o0.x += bb0.x; o0.y += bb0.y; o0.z += bb0.z; o0.w += bb0.w;
                o1.x += bb1.x; o1.y += bb1.y; o1.z += bb1.z; o1.w += bb1.w;
            }
            if (RELU) {
                o0.x = fmaxf(o0.x, 0.f); o0.y = fmaxf(o0.y, 0.f);
                o0.z = fmaxf(o0.z, 0.f); o0.w = fmaxf(o0.w, 0.f);
                o1.x = fmaxf(o1.x, 0.f); o1.y = fmaxf(o1.y, 0.f);
                o1.z = fmaxf(o1.z, 0.f); o1.w = fmaxf(o1.w, 0.f);
            }
            if (RES) {
                float4 r0 = *(const float4*)&res[(size_t)m * Co + n0];
                float4 r1 = *(const float4*)&res[(size_t)m * Co + n0 + 4];
                o0.x += r0.x; o0.y += r0.y; o0.z += r0.z; o0.w += r0.w;
                o1.x += r1.x; o1.y += r1.y; o1.z += r1.z; o1.w += r1.w;
            }
            *(float4*)&Y[(size_t)m * Co + n0] = o0;
            *(float4*)&Y[(size_t)m * Co + n0 + 4] = o1;
        }
    }
}

// ---------------- edge bias: g_eb[e,h] = edge_feat[e,:] . We[h,:] + be[h] ----------------
__global__ void __launch_bounds__(256)
eb_kernel(const float* __restrict__ ef, const float* __restrict__ We,
          const float* __restrict__ be) {
    __shared__ float sWe[HH * EDD];
    __shared__ float sbe[HH];
    for (int i = threadIdx.x; i < HH * EDD; i += 256) sWe[i] = We[i];
    if (threadIdx.x < HH) sbe[threadIdx.x] = be[threadIdx.x];
    __syncthreads();

    const int e = blockIdx.x * 256 + threadIdx.x;  // EE % 256 == 0
    const float4* efp = (const float4*)(ef + (size_t)e * EDD);
    float acc[HH];
#pragma unroll
    for (int h = 0; h < HH; h++) acc[h] = sbe[h];
#pragma unroll
    for (int j4 = 0; j4 < EDD / 4; j4++) {
        float4 v = efp[j4];
#pragma unroll
        for (int h = 0; h < HH; h++) {
            float4 w = *(const float4*)&sWe[h * EDD + j4 * 4];
            acc[h] += v.x * w.x + v.y * w.y + v.z * w.z + v.w * w.w;
        }
    }
    float4 o0 = make_float4(acc[0], acc[1], acc[2], acc[3]);
    float4 o1 = make_float4(acc[4], acc[5], acc[6], acc[7]);
    ((float4*)g_eb)[(size_t)e * 2 + 0] = o0;
    ((float4*)g_eb)[(size_t)e * 2 + 1] = o1;
}

// ---------------- scores + segment max (warp per edge) ----------------
__global__ void __launch_bounds__(256)
score_kernel(const int* __restrict__ src, const int* __restrict__ dst) {
    const int warpId = (blockIdx.x * 256 + threadIdx.x) >> 5;
    const int lane = threadIdx.x & 31;
    if (warpId >= EE) return;
    const int e = warpId;
    const int s = __ldg(&src[e]);
    const int d = __ldg(&dst[e]);
    float4 qv = ((const float4*)g_qd)[(size_t)d * 32 + lane];
    float4 kv = ((const float4*)g_kd)[(size_t)s * 32 + lane];
    float p = qv.x * kv.x + qv.y * kv.y + qv.z * kv.z + qv.w * kv.w;
    p += __shfl_xor_sync(0xffffffffu, p, 1);
    p += __shfl_xor_sync(0xffffffffu, p, 2);
    if ((lane & 3) == 0) {
        const int h = lane >> 2;
        float sc = p * 0.25f + g_eb[(size_t)e * HH + h];  // 1/sqrt(16)
        g_sc[(size_t)e * HH + h] = sc;
        atomicMax(&g_smax[(size_t)d * HH + h], ordEnc(sc));
    }
}

// ---------------- fused exp + denom + unnormalized scatter (warp per edge) ----------------
__global__ void __launch_bounds__(256)
expagg_kernel(const int* __restrict__ src, const int* __restrict__ dst) {
    const int warpId = (blockIdx.x * 256 + threadIdx.x) >> 5;
    const int lane = threadIdx.x & 31;
    if (warpId >= EE) return;
    const int e = warpId;
    const int s = __ldg(&src[e]);
    const int d = __ldg(&dst[e]);
    float ex = 0.f;
    if (lane < HH) {
        const float sc = g_sc[(size_t)e * HH + lane];
        const float m = ordDec(g_smax[(size_t)d * HH + lane]);
        ex = __expf(sc - m);
        atomicAdd(&g_den[(size_t)d * HH + lane], ex);
    }
    const float a = __shfl_sync(0xffffffffu, ex, lane >> 2);  // head of this chunk
    float4 vv = ((const float4*)g_vd)[(size_t)s * 32 + lane];
    float* p = g_agg + (size_t)d * CD + lane * 4;
    asm volatile("red.global.add.v4.f32 [%0], {%1,%2,%3,%4};"
                 :: "l"(p), "f"(vv.x * a), "f"(vv.y * a), "f"(vv.z * a), "f"(vv.w * a)
                 : "memory");
}

// ---------------- normalize agg by denom ----------------
__global__ void __launch_bounds__(256)
div_kernel() {
    const int i = blockIdx.x * 256 + threadIdx.x;  // over NN*32 float4s
    if (i >= NN * (CD / 4)) return;
    const int node = i >> 5;
    const int chunk = i & 31;
    const int h = chunk >> 2;
    const float den = g_den[(size_t)node * HH + h];
    const float inv = (den > 0.f) ? (1.f / den) : 0.f;
    float4 v = ((float4*)g_agg)[i];
    v.x *= inv; v.y *= inv; v.z *= inv; v.w *= inv;
    ((float4*)g_agg)[i] = v;
}

// ---------------- batchnorm stats (column sums / sumsq) ----------------
__global__ void __launch_bounds__(128)
bn_stats_kernel(const float* __restrict__ X, float* __restrict__ sums) {
    const int c = threadIdx.x;  // 128 columns
    const int r0 = blockIdx.x * 256;
    const int rend = min(r0 + 256, NN);
    float s = 0.f, s2 = 0.f;
    for (int r = r0; r < rend; r++) {
        float v = X[(size_t)r * CD + c];
        s += v; s2 += v * v;
    }
    atomicAdd(&sums[c], s);
    atomicAdd(&sums[CD + c], s2);
}

// ---------------- batchnorm apply ----------------
__global__ void __launch_bounds__(256)
bn_apply_kernel(const float* __restrict__ X, float* __restrict__ Y,
                const float* __restrict__ sums,
                const float* __restrict__ g, const float* __restrict__ b) {
    const int i = blockIdx.x * 256 + threadIdx.x;  // NN*CD % 256 == 0
    const int c = i & (CD - 1);
    const float inv = 1.f / (float)NN;
    const float mu = sums[c] * inv;
    const float var = sums[CD + c] * inv - mu * mu;
    const float rs = rsqrtf(var + EPS);
    Y[i] = (X[i] - mu) * rs * g[c] + b[c];
}

// ---------------- launcher ----------------
extern "C" void kernel_launch(void* const* d_in, const int* in_sizes, int n_in,
                              void* d_out, int out_size) {
    const float* q   = (const float*)d_in[0];
    const float* k   = (const float*)d_in[1];
    const float* v   = (const float*)d_in[2];
    const float* ef  = (const float*)d_in[3];
    const int*   src = (const int*)d_in[4];
    const int*   dst = (const int*)d_in[5];
    const float* Wq  = (const float*)d_in[6];
    const float* Wk  = (const float*)d_in[7];
    const float* Wv  = (const float*)d_in[8];
    const float* We  = (const float*)d_in[9];
    const float* be  = (const float*)d_in[10];
    const float* Wo  = (const float*)d_in[11];
    const float* W1  = (const float*)d_in[12];
    const float* b1  = (const float*)d_in[13];
    const float* W2  = (const float*)d_in[14];
    const float* b2  = (const float*)d_in[15];
    const float* g1  = (const float*)d_in[16];
    const float* bt1 = (const float*)d_in[17];
    const float* g2  = (const float*)d_in[18];
    const float* bt2 = (const float*)d_in[19];
    float* out = (float*)d_out;

    float* p_qd; cudaGetSymbolAddress((void**)&p_qd, g_qd);
    float* p_kd; cudaGetSymbolAddress((void**)&p_kd, g_kd);
    float* p_vd; cudaGetSymbolAddress((void**)&p_vd, g_vd);
    float* p_agg; cudaGetSymbolAddress((void**)&p_agg, g_agg);
    float* p_rst; cudaGetSymbolAddress((void**)&p_rst, g_rst);
    float* p_h1; cudaGetSymbolAddress((void**)&p_h1, g_h1);
    float* p_h2; cudaGetSymbolAddress((void**)&p_h2, g_h2);
    float* p_stats; cudaGetSymbolAddress((void**)&p_stats, g_stats);

    init_kernel<<<4096, 256>>>();

    const dim3 gC(313, 1);   // (40000+127)/128, 128/128
    const dim3 gH(313, 2);   // FFN hidden: 256/128

    // projections
    sgemm_kernel<false, false, false><<<gC, 256>>>(q, Wq, nullptr, nullptr, p_qd, NN, CD, CD);
    sgemm_kernel<false, false, false><<<gC, 256>>>(k, Wk, nullptr, nullptr, p_kd, NN, CD, CD);
    sgemm_kernel<false, false, false><<<gC, 256>>>(v, Wv, nullptr, nullptr, p_vd, NN, CD, CD);

    // edge phase
    eb_kernel<<<EE / 256, 256>>>(ef, We, be);
    score_kernel<<<EE / 8, 256>>>(src, dst);
    expagg_kernel<<<EE / 8, 256>>>(src, dst);
    div_kernel<<<(NN * (CD / 4) + 255) / 256, 256>>>();

    // out proj + residual, BN1
    sgemm_kernel<false, false, true><<<gC, 256>>>(p_agg, Wo, nullptr, q, p_rst, NN, CD, CD);
    bn_stats_kernel<<<(NN + 255) / 256, 128>>>(p_rst, p_stats);
    bn_apply_kernel<<<NN * CD / 256, 256>>>(p_rst, p_rst, p_stats, g1, bt1);

    // FFN + residual, BN2
    sgemm_kernel<true, true, false><<<gH, 256>>>(p_rst, W1, b1, nullptr, p_h1, NN, CD, C2);
    sgemm_kernel<false, true, true><<<gC, 256>>>(p_h1, W2, b2, p_rst, p_h2, NN, C2, CD);
    bn_stats_kernel<<<(NN + 255) / 256, 128>>>(p_h2, p_stats + 2 * CD);
    bn_apply_kernel<<<NN * CD / 256, 256>>>(p_h2, out, p_stats + 2 * CD, g2, bt2);
}

// round 6
// speedup vs baseline: 1.3414x; 1.3414x over previous
#include <cuda_runtime.h>
#include <cuda_bf16.h>
#include <mma.h>
#include <cstdint>

using namespace nvcuda;

// ---------------- problem constants ----------------
#define NN 40000      // nodes
#define EE 640000     // edges
#define CD 128        // channels (= IN = H*D)
#define HH 8          // heads
#define DD 16         // dim per head
#define EDD 64        // edge feature dim
#define C2 256        // FFN hidden
#define EPS 1e-5f

// ---------------- scratch (static device globals; no allocs allowed) ----------------
__device__ float    g_qd[(size_t)NN * CD];
__device__ float    g_kd[(size_t)NN * CD];
__device__ float    g_vd[(size_t)NN * CD];
__device__ float    g_eb[(size_t)EE * HH];    // per-edge bias
__device__ float    g_sc[(size_t)EE * HH];    // raw scores
__device__ unsigned g_smax[(size_t)NN * HH];  // ordered-uint encoded max
__device__ float    g_den[(size_t)NN * HH];
__device__ float    g_agg[(size_t)NN * CD];
__device__ float    g_rst[(size_t)NN * CD];
__device__ float    g_h1[(size_t)NN * C2];
__device__ float    g_h2[(size_t)NN * CD];
__device__ float    g_stats[4 * CD];          // [sum1, sq1, sum2, sq2]

// ---------------- helpers ----------------
__device__ __forceinline__ unsigned ordEnc(float f) {
    unsigned b = __float_as_uint(f);
    return (b & 0x80000000u) ? ~b : (b | 0x80000000u);
}
__device__ __forceinline__ float ordDec(unsigned u) {
    unsigned b = (u & 0x80000000u) ? (u ^ 0x80000000u) : ~u;
    return __uint_as_float(b);
}

// ---------------- init: zero accumulators every call (graph replays!) ----------------
__global__ void init_kernel() {
    int i = blockIdx.x * blockDim.x + threadIdx.x;
    int stride = gridDim.x * blockDim.x;
    for (int j = i; j < NN * CD; j += stride) g_agg[j] = 0.f;
    for (int j = i; j < NN * HH; j += stride) {
        g_den[j] = 0.f;
        g_smax[j] = 0x007FFFFFu;  // ordEnc(-inf)
    }
    if (i < 4 * CD) g_stats[i] = 0.f;
}

// ---------------- WMMA bf16-split GEMM: Y[M,Co] = X[M,K] @ W[Co,K]^T ----------------
// fp32 = hi(bf16) + lo(bf16);  D = Ah*Bh + Ah*Bl + Al*Bh  (fp32 accum).
// CTA tile 128x128, 8 warps each 32x64, K chunked by 64 into padded smem.
#define LDS_AB 72                       // bf16 row stride (pad 64 -> 72)
#define OFF_AH 0
#define OFF_AL (OFF_AH + 128 * LDS_AB * 2)   // 18432
#define OFF_BH (OFF_AL + 128 * LDS_AB * 2)   // 36864
#define OFF_BL (OFF_BH + 128 * LDS_AB * 2)   // 55296
#define SMEM_TC (OFF_BL + 128 * LDS_AB * 2)  // 73728 bytes
#define LDS_C 132                       // fp32 epilogue stage row stride

__device__ __forceinline__ void cvt_store(char* smem, int offH, int offL,
                                          int row, int c4, float4 v) {
    __nv_bfloat162 h0 = __floats2bfloat162_rn(v.x, v.y);
    __nv_bfloat162 h1 = __floats2bfloat162_rn(v.z, v.w);
    float2 f0 = __bfloat1622float2(h0);
    float2 f1 = __bfloat1622float2(h1);
    __nv_bfloat162 l0 = __floats2bfloat162_rn(v.x - f0.x, v.y - f0.y);
    __nv_bfloat162 l1 = __floats2bfloat162_rn(v.z - f1.x, v.w - f1.y);
    uint2 ph, pl;
    ph.x = *(uint32_t*)&h0; ph.y = *(uint32_t*)&h1;
    pl.x = *(uint32_t*)&l0; pl.y = *(uint32_t*)&l1;
    *(uint2*)(smem + offH + ((size_t)row * LDS_AB + c4) * 2) = ph;
    *(uint2*)(smem + offL + ((size_t)row * LDS_AB + c4) * 2) = pl;
}

template <bool RELU, bool BIAS, bool RES>
__global__ void __launch_bounds__(256, 2)
tc_gemm_kernel(const float* __restrict__ X, const float* __restrict__ W,
               const float* __restrict__ bias, const float* __restrict__ res,
               float* __restrict__ Y, int M, int K, int Co) {
    extern __shared__ char smem[];
    const int tid = threadIdx.x;
    const int warp = tid >> 5;
    const int bm = blockIdx.x * 128;
    const int bn = blockIdx.y * 128;
    const int wm = (warp & 3) * 32;     // warp row offset within tile
    const int wn = (warp >> 2) * 64;    // warp col offset within tile

    wmma::fragment<wmma::accumulator, 16, 16, 16, float> acc[2][4];
#pragma unroll
    for (int i = 0; i < 2; i++)
#pragma unroll
        for (int j = 0; j < 4; j++)
            wmma::fill_fragment(acc[i][j], 0.f);

    const __nv_bfloat16* sAh = (const __nv_bfloat16*)(smem + OFF_AH);
    const __nv_bfloat16* sAl = (const __nv_bfloat16*)(smem + OFF_AL);
    const __nv_bfloat16* sBh = (const __nv_bfloat16*)(smem + OFF_BH);
    const __nv_bfloat16* sBl = (const __nv_bfloat16*)(smem + OFF_BL);

    const int nch = K >> 6;
    for (int ch = 0; ch < nch; ch++) {
        const int kc0 = ch << 6;
        __syncthreads();   // previous iteration's frag loads done before overwrite
        // convert chunk: 128 rows x 64 cols fp32 -> bf16 hi/lo
#pragma unroll
        for (int it = 0; it < 8; it++) {
            const int idx = tid + it * 256;        // 0..2047
            const int row = idx >> 4;              // 0..127
            const int c4 = (idx & 15) << 2;        // 0..60
            {   // A tile (clamp tail rows; dup-read safe, epilogue guards store)
                const int r = min(bm + row, M - 1);
                float4 v = *(const float4*)(X + (size_t)r * K + kc0 + c4);
                cvt_store(smem, OFF_AH, OFF_AL, row, c4, v);
            }
            {   // B tile (Co always a multiple of 128)
                float4 v = *(const float4*)(W + (size_t)(bn + row) * K + kc0 + c4);
                cvt_store(smem, OFF_BH, OFF_BL, row, c4, v);
            }
        }
        __syncthreads();

#pragma unroll
        for (int ks = 0; ks < 4; ks++) {
            const int k0 = ks * 16;
            wmma::fragment<wmma::matrix_a, 16, 16, 16, __nv_bfloat16, wmma::row_major> ah[2], al[2];
#pragma unroll
            for (int i = 0; i < 2; i++) {
                wmma::load_matrix_sync(ah[i], sAh + (size_t)(wm + 16 * i) * LDS_AB + k0, LDS_AB);
                wmma::load_matrix_sync(al[i], sAl + (size_t)(wm + 16 * i) * LDS_AB + k0, LDS_AB);
            }
#pragma unroll
            for (int j = 0; j < 4; j++) {
                wmma::fragment<wmma::matrix_b, 16, 16, 16, __nv_bfloat16, wmma::col_major> bh, bl;
                wmma::load_matrix_sync(bh, sBh + (size_t)(wn + 16 * j) * LDS_AB + k0, LDS_AB);
                wmma::load_matrix_sync(bl, sBl + (size_t)(wn + 16 * j) * LDS_AB + k0, LDS_AB);
#pragma unroll
                for (int i = 0; i < 2; i++) {
                    wmma::mma_sync(acc[i][j], ah[i], bh, acc[i][j]);
                    wmma::mma_sync(acc[i][j], ah[i], bl, acc[i][j]);
                    wmma::mma_sync(acc[i][j], al[i], bh, acc[i][j]);
                }
            }
        }
    }

    // epilogue: stage fp32 tile in smem, then fused bias/relu/residual store
    __syncthreads();
    float* sC = (float*)smem;
#pragma unroll
    for (int i = 0; i < 2; i++)
#pragma unroll
        for (int j = 0; j < 4; j++)
            wmma::store_matrix_sync(sC + (size_t)(wm + 16 * i) * LDS_C + wn + 16 * j,
                                    acc[i][j], LDS_C, wmma::mem_row_major);
    __syncthreads();

#pragma unroll
    for (int it = 0; it < 16; it++) {
        const int idx = tid + it * 256;            // 0..4095
        const int row = idx >> 5;                  // 0..127
        const int c = (idx & 31) << 2;             // 0..124
        const int m = bm + row;
        if (m < M) {
            const int n = bn + c;
            float4 o = *(const float4*)(sC + (size_t)row * LDS_C + c);
            if (BIAS) {
                float4 b4 = *(const float4*)&bias[n];
                o.x += b4.x; o.y += b4.y; o.z += b4.z; o.w += b4.w;
            }
            if (RELU) {
                o.x = fmaxf(o.x, 0.f); o.y = fmaxf(o.y, 0.f);
                o.z = fmaxf(o.z, 0.f); o.w = fmaxf(o.w, 0.f);
            }
            if (RES) {
                float4 r4 = *(const float4*)&res[(size_t)m * Co + n];
                o.x += r4.x; o.y += r4.y; o.z += r4.z; o.w += r4.w;
            }
            *(float4*)&Y[(size_t)m * Co + n] = o;
        }
    }
}

// ---------------- edge bias: g_eb[e,h] = edge_feat[e,:] . We[h,:] + be[h] ----------------
__global__ void __launch_bounds__(256)
eb_kernel(const float* __restrict__ ef, const float* __restrict__ We,
          const float* __restrict__ be) {
    __shared__ float sWe[HH * EDD];
    __shared__ float sbe[HH];
    for (int i = threadIdx.x; i < HH * EDD; i += 256) sWe[i] = We[i];
    if (threadIdx.x < HH) sbe[threadIdx.x] = be[threadIdx.x];
    __syncthreads();

    const int e = blockIdx.x * 256 + threadIdx.x;  // EE % 256 == 0
    const float4* efp = (const float4*)(ef + (size_t)e * EDD);
    float acc[HH];
#pragma unroll
    for (int h = 0; h < HH; h++) acc[h] = sbe[h];
#pragma unroll
    for (int j4 = 0; j4 < EDD / 4; j4++) {
        float4 v = efp[j4];
#pragma unroll
        for (int h = 0; h < HH; h++) {
            float4 w = *(const float4*)&sWe[h * EDD + j4 * 4];
            acc[h] += v.x * w.x + v.y * w.y + v.z * w.z + v.w * w.w;
        }
    }
    float4 o0 = make_float4(acc[0], acc[1], acc[2], acc[3]);
    float4 o1 = make_float4(acc[4], acc[5], acc[6], acc[7]);
    ((float4*)g_eb)[(size_t)e * 2 + 0] = o0;
    ((float4*)g_eb)[(size_t)e * 2 + 1] = o1;
}

// ---------------- scores + segment max (warp per edge) ----------------
__global__ void __launch_bounds__(256)
score_kernel(const int* __restrict__ src, const int* __restrict__ dst) {
    const int warpId = (blockIdx.x * 256 + threadIdx.x) >> 5;
    const int lane = threadIdx.x & 31;
    if (warpId >= EE) return;
    const int e = warpId;
    const int s = __ldg(&src[e]);
    const int d = __ldg(&dst[e]);
    float4 qv = ((const float4*)g_qd)[(size_t)d * 32 + lane];
    float4 kv = ((const float4*)g_kd)[(size_t)s * 32 + lane];
    float p = qv.x * kv.x + qv.y * kv.y + qv.z * kv.z + qv.w * kv.w;
    p += __shfl_xor_sync(0xffffffffu, p, 1);
    p += __shfl_xor_sync(0xffffffffu, p, 2);
    if ((lane & 3) == 0) {
        const int h = lane >> 2;
        float sc = p * 0.25f + g_eb[(size_t)e * HH + h];  // 1/sqrt(16)
        g_sc[(size_t)e * HH + h] = sc;
        atomicMax(&g_smax[(size_t)d * HH + h], ordEnc(sc));
    }
}

// ---------------- fused exp + denom + unnormalized scatter (warp per edge) ----------------
__global__ void __launch_bounds__(256)
expagg_kernel(const int* __restrict__ src, const int* __restrict__ dst) {
    const int warpId = (blockIdx.x * 256 + threadIdx.x) >> 5;
    const int lane = threadIdx.x & 31;
    if (warpId >= EE) return;
    const int e = warpId;
    const int s = __ldg(&src[e]);
    const int d = __ldg(&dst[e]);
    float ex = 0.f;
    if (lane < HH) {
        const float sc = g_sc[(size_t)e * HH + lane];
        const float m = ordDec(g_smax[(size_t)d * HH + lane]);
        ex = __expf(sc - m);
        atomicAdd(&g_den[(size_t)d * HH + lane], ex);
    }
    const float a = __shfl_sync(0xffffffffu, ex, lane >> 2);  // head of this chunk
    float4 vv = ((const float4*)g_vd)[(size_t)s * 32 + lane];
    float* p = g_agg + (size_t)d * CD + lane * 4;
    asm volatile("red.global.add.v4.f32 [%0], {%1,%2,%3,%4};"
                 :: "l"(p), "f"(vv.x * a), "f"(vv.y * a), "f"(vv.z * a), "f"(vv.w * a)
                 : "memory");
}

// ---------------- normalize agg by denom ----------------
__global__ void __launch_bounds__(256)
div_kernel() {
    const int i = blockIdx.x * 256 + threadIdx.x;  // over NN*32 float4s
    if (i >= NN * (CD / 4)) return;
    const int node = i >> 5;
    const int chunk = i & 31;
    const int h = chunk >> 2;
    const float den = g_den[(size_t)node * HH + h];
    const float inv = (den > 0.f) ? (1.f / den) : 0.f;
    float4 v = ((float4*)g_agg)[i];
    v.x *= inv; v.y *= inv; v.z *= inv; v.w *= inv;
    ((float4*)g_agg)[i] = v;
}

// ---------------- batchnorm stats (column sums / sumsq) ----------------
__global__ void __launch_bounds__(128)
bn_stats_kernel(const float* __restrict__ X, float* __restrict__ sums) {
    const int c = threadIdx.x;  // 128 columns
    const int r0 = blockIdx.x * 256;
    const int rend = min(r0 + 256, NN);
    float s = 0.f, s2 = 0.f;
    for (int r = r0; r < rend; r++) {
        float v = X[(size_t)r * CD + c];
        s += v; s2 += v * v;
    }
    atomicAdd(&sums[c], s);
    atomicAdd(&sums[CD + c], s2);
}

// ---------------- batchnorm apply ----------------
__global__ void __launch_bounds__(256)
bn_apply_kernel(const float* __restrict__ X, float* __restrict__ Y,
                const float* __restrict__ sums,
                const float* __restrict__ g, const float* __restrict__ b) {
    const int i = blockIdx.x * 256 + threadIdx.x;  // NN*CD % 256 == 0
    const int c = i & (CD - 1);
    const float inv = 1.f / (float)NN;
    const float mu = sums[c] * inv;
    const float var = sums[CD + c] * inv - mu * mu;
    const float rs = rsqrtf(var + EPS);
    Y[i] = (X[i] - mu) * rs * g[c] + b[c];
}

// ---------------- launcher ----------------
extern "C" void kernel_launch(void* const* d_in, const int* in_sizes, int n_in,
                              void* d_out, int out_size) {
    const float* q   = (const float*)d_in[0];
    const float* k   = (const float*)d_in[1];
    const float* v   = (const float*)d_in[2];
    const float* ef  = (const float*)d_in[3];
    const int*   src = (const int*)d_in[4];
    const int*   dst = (const int*)d_in[5];
    const float* Wq  = (const float*)d_in[6];
    const float* Wk  = (const float*)d_in[7];
    const float* Wv  = (const float*)d_in[8];
    const float* We  = (const float*)d_in[9];
    const float* be  = (const float*)d_in[10];
    const float* Wo  = (const float*)d_in[11];
    const float* W1  = (const float*)d_in[12];
    const float* b1  = (const float*)d_in[13];
    const float* W2  = (const float*)d_in[14];
    const float* b2  = (const float*)d_in[15];
    const float* g1  = (const float*)d_in[16];
    const float* bt1 = (const float*)d_in[17];
    const float* g2  = (const float*)d_in[18];
    const float* bt2 = (const float*)d_in[19];
    float* out = (float*)d_out;

    float* p_qd; cudaGetSymbolAddress((void**)&p_qd, g_qd);
    float* p_kd; cudaGetSymbolAddress((void**)&p_kd, g_kd);
    float* p_vd; cudaGetSymbolAddress((void**)&p_vd, g_vd);
    float* p_agg; cudaGetSymbolAddress((void**)&p_agg, g_agg);
    float* p_rst; cudaGetSymbolAddress((void**)&p_rst, g_rst);
    float* p_h1; cudaGetSymbolAddress((void**)&p_h1, g_h1);
    float* p_h2; cudaGetSymbolAddress((void**)&p_h2, g_h2);
    float* p_stats; cudaGetSymbolAddress((void**)&p_stats, g_stats);

    // raise dynamic smem limit for the WMMA GEMM variants (no-op after first call)
    cudaFuncSetAttribute(tc_gemm_kernel<false, false, false>, cudaFuncAttributeMaxDynamicSharedMemorySize, SMEM_TC);
    cudaFuncSetAttribute(tc_gemm_kernel<false, false, true>,  cudaFuncAttributeMaxDynamicSharedMemorySize, SMEM_TC);
    cudaFuncSetAttribute(tc_gemm_kernel<true,  true,  false>, cudaFuncAttributeMaxDynamicSharedMemorySize, SMEM_TC);
    cudaFuncSetAttribute(tc_gemm_kernel<false, true,  true>,  cudaFuncAttributeMaxDynamicSharedMemorySize, SMEM_TC);

    init_kernel<<<4096, 256>>>();

    const dim3 gC(313, 1);   // ceil(40000/128) x (128/128)
    const dim3 gH(313, 2);   // FFN hidden: 256/128

    // projections (WMMA bf16-split)
    tc_gemm_kernel<false, false, false><<<gC, 256, SMEM_TC>>>(q, Wq, nullptr, nullptr, p_qd, NN, CD, CD);
    tc_gemm_kernel<false, false, false><<<gC, 256, SMEM_TC>>>(k, Wk, nullptr, nullptr, p_kd, NN, CD, CD);
    tc_gemm_kernel<false, false, false><<<gC, 256, SMEM_TC>>>(v, Wv, nullptr, nullptr, p_vd, NN, CD, CD);

    // edge phase
    eb_kernel<<<EE / 256, 256>>>(ef, We, be);
    score_kernel<<<EE / 8, 256>>>(src, dst);
    expagg_kernel<<<EE / 8, 256>>>(src, dst);
    div_kernel<<<(NN * (CD / 4) + 255) / 256, 256>>>();

    // out proj + residual, BN1
    tc_gemm_kernel<false, false, true><<<gC, 256, SMEM_TC>>>(p_agg, Wo, nullptr, q, p_rst, NN, CD, CD);
    bn_stats_kernel<<<(NN + 255) / 256, 128>>>(p_rst, p_stats);
    bn_apply_kernel<<<NN * CD / 256, 256>>>(p_rst, p_rst, p_stats, g1, bt1);

    // FFN + residual, BN2
    tc_gemm_kernel<true, true, false><<<gH, 256, SMEM_TC>>>(p_rst, W1, b1, nullptr, p_h1, NN, CD, C2);
    tc_gemm_kernel<false, true, true><<<gC, 256, SMEM_TC>>>(p_h1, W2, b2, p_rst, p_h2, NN, C2, CD);
    bn_stats_kernel<<<(NN + 255) / 256, 128>>>(p_h2, p_stats + 2 * CD);
    bn_apply_kernel<<<NN * CD / 256, 256>>>(p_h2, out, p_stats + 2 * CD, g2, bt2);
}

// round 7
// speedup vs baseline: 1.4901x; 1.1108x over previous
#include <cuda_runtime.h>
#include <cuda_bf16.h>
#include <mma.h>
#include <cstdint>

using namespace nvcuda;

// ---------------- problem constants ----------------
#define NN 40000      // nodes
#define EE 640000     // edges
#define CD 128        // channels (= IN = H*D)
#define HH 8          // heads
#define DD 16         // dim per head
#define EDD 64        // edge feature dim
#define C2 256        // FFN hidden
#define EPS 1e-5f

// ---------------- scratch (static device globals; no allocs allowed) ----------------
__device__ float    g_qd[(size_t)NN * CD];
__device__ float    g_kd[(size_t)NN * CD];
__device__ float    g_vd[(size_t)NN * CD];
__device__ float    g_eb[(size_t)EE * HH];    // per-edge bias
__device__ float    g_sc[(size_t)EE * HH];    // scores -> exp weights (CSR order)
__device__ float    g_agg[(size_t)NN * CD];
__device__ float    g_rst[(size_t)NN * CD];
__device__ float    g_h1[(size_t)NN * C2];
__device__ float    g_h2[(size_t)NN * CD];
__device__ float    g_stats[4 * CD];          // [sum1, sq1, sum2, sq2]
// CSR
__device__ int      g_cnt[NN];
__device__ int      g_pos[NN];
__device__ int      g_row[NN + 1];
__device__ int      g_esrc[EE];
__device__ int      g_eid[EE];
// preconverted weights (bf16 hi/lo): Wq 0, Wk 16384, Wv 32768, Wo 49152, W1 65536, W2 98304
#define WOFF_Q  0
#define WOFF_K  16384
#define WOFF_V  32768
#define WOFF_O  49152
#define WOFF_1  65536
#define WOFF_2  98304
#define WTOT    131072
__device__ __nv_bfloat16 g_wh[WTOT];
__device__ __nv_bfloat16 g_wl[WTOT];

// ---------------- init: zero counters every call (graph replays!) ----------------
__global__ void init_kernel() {
    int i = blockIdx.x * blockDim.x + threadIdx.x;
    if (i < NN) { g_cnt[i] = 0; g_pos[i] = 0; }
    if (i < 4 * CD) g_stats[i] = 0.f;
}

// ---------------- weight preconversion fp32 -> bf16 hi/lo ----------------
__global__ void wconv_kernel(const float* __restrict__ W, int n, int off) {
    int i = blockIdx.x * blockDim.x + threadIdx.x;
    if (i < n) {
        float v = W[i];
        __nv_bfloat16 h = __float2bfloat16(v);
        g_wh[off + i] = h;
        g_wl[off + i] = __float2bfloat16(v - __bfloat162float(h));
    }
}

// ---------------- CSR build ----------------
__global__ void hist_kernel(const int* __restrict__ dst) {
    int e = blockIdx.x * 256 + threadIdx.x;  // EE % 256 == 0
    atomicAdd(&g_cnt[dst[e]], 1);
}

__global__ void __launch_bounds__(1024)
scan_kernel() {
    __shared__ int sdata[1024];
    const int t = threadIdx.x;
    int carry = 0;
    for (int base = 0; base < NN; base += 1024) {
        int x = (base + t < NN) ? g_cnt[base + t] : 0;
        sdata[t] = x;
        __syncthreads();
#pragma unroll
        for (int off = 1; off < 1024; off <<= 1) {
            int v = (t >= off) ? sdata[t - off] : 0;
            __syncthreads();
            sdata[t] += v;
            __syncthreads();
        }
        if (base + t < NN) g_row[base + t] = carry + sdata[t] - x;
        carry += sdata[1023];
        __syncthreads();
    }
    if (t == 0) g_row[NN] = EE;
}

__global__ void scatter_kernel(const int* __restrict__ src, const int* __restrict__ dst) {
    int e = blockIdx.x * 256 + threadIdx.x;
    const int d = dst[e];
    int p = atomicAdd(&g_pos[d], 1);
    int o = g_row[d] + p;
    g_esrc[o] = src[e];
    g_eid[o] = e;
}

// ---------------- fused per-node attention (warp per node, no atomics) ----------------
__global__ void __launch_bounds__(256)
attn_kernel() {
    const int warpId = (blockIdx.x * 256 + threadIdx.x) >> 5;
    const int lane = threadIdx.x & 31;
    if (warpId >= NN) return;
    const int n = warpId;
    const int r0 = g_row[n], r1 = g_row[n + 1];
    const int h = lane >> 2;

    float4 qv = ((const float4*)g_qd)[(size_t)n * 32 + lane];

    // pass 1: scores + per-head max
    float mx = -3.0e38f;
    for (int i = r0; i < r1; i++) {
        const int s = g_esrc[i];
        const int e = g_eid[i];
        float4 kv = ((const float4*)g_kd)[(size_t)s * 32 + lane];
        float p = qv.x * kv.x + qv.y * kv.y + qv.z * kv.z + qv.w * kv.w;
        p += __shfl_xor_sync(0xffffffffu, p, 1);
        p += __shfl_xor_sync(0xffffffffu, p, 2);
        float sc = p * 0.25f + __ldg(&g_eb[(size_t)e * HH + h]);  // 1/sqrt(16)
        mx = fmaxf(mx, sc);
        g_sc[(size_t)i * HH + h] = sc;   // 4 lanes store same value, one wins
    }
    // pass 2: exp + denom
    float den = 0.f;
    for (int i = r0; i < r1; i++) {
        float sc = g_sc[(size_t)i * HH + h];
        float ex = __expf(sc - mx);
        den += ex;
        g_sc[(size_t)i * HH + h] = ex;
    }
    const float inv = (den > 0.f) ? (1.f / den) : 0.f;
    // pass 3: weighted aggregation
    float4 acc = make_float4(0.f, 0.f, 0.f, 0.f);
    for (int i = r0; i < r1; i++) {
        const int s = g_esrc[i];
        const float a = g_sc[(size_t)i * HH + h];
        float4 vv = ((const float4*)g_vd)[(size_t)s * 32 + lane];
        acc.x += vv.x * a; acc.y += vv.y * a; acc.z += vv.z * a; acc.w += vv.w * a;
    }
    acc.x *= inv; acc.y *= inv; acc.z *= inv; acc.w *= inv;
    ((float4*)g_agg)[(size_t)n * 32 + lane] = acc;
}

// ---------------- WMMA bf16-split GEMM: Y[M,Co] = X[M,K] @ W[Co,K]^T ----------------
// A: fp32 converted in-kernel to hi/lo; B: preconverted bf16 hi/lo in global.
#define LDS_AB 72                       // bf16 row stride (pad 64 -> 72)
#define OFF_AH 0
#define OFF_AL (OFF_AH + 128 * LDS_AB * 2)   // 18432
#define OFF_BH (OFF_AL + 128 * LDS_AB * 2)   // 36864
#define OFF_BL (OFF_BH + 128 * LDS_AB * 2)   // 55296
#define SMEM_TC (OFF_BL + 128 * LDS_AB * 2)  // 73728 bytes
#define LDS_C 132                       // fp32 epilogue stage row stride

__device__ __forceinline__ void cvt_storeA(char* smem, int row, int c4, float4 v) {
    __nv_bfloat162 h0 = __floats2bfloat162_rn(v.x, v.y);
    __nv_bfloat162 h1 = __floats2bfloat162_rn(v.z, v.w);
    float2 f0 = __bfloat1622float2(h0);
    float2 f1 = __bfloat1622float2(h1);
    __nv_bfloat162 l0 = __floats2bfloat162_rn(v.x - f0.x, v.y - f0.y);
    __nv_bfloat162 l1 = __floats2bfloat162_rn(v.z - f1.x, v.w - f1.y);
    uint2 ph, pl;
    ph.x = *(uint32_t*)&h0; ph.y = *(uint32_t*)&h1;
    pl.x = *(uint32_t*)&l0; pl.y = *(uint32_t*)&l1;
    *(uint2*)(smem + OFF_AH + ((size_t)row * LDS_AB + c4) * 2) = ph;
    *(uint2*)(smem + OFF_AL + ((size_t)row * LDS_AB + c4) * 2) = pl;
}

template <bool RELU, bool BIAS, bool RES>
__global__ void __launch_bounds__(256, 2)
tc_gemm_kernel(const float* __restrict__ X,
               const __nv_bfloat16* __restrict__ WH, const __nv_bfloat16* __restrict__ WL,
               const float* __restrict__ bias, const float* __restrict__ res,
               float* __restrict__ Y, int M, int K, int Co) {
    extern __shared__ char smem[];
    const int tid = threadIdx.x;
    const int warp = tid >> 5;
    const int bm = blockIdx.x * 128;
    const int bn = blockIdx.y * 128;
    const int wm = (warp & 3) * 32;
    const int wn = (warp >> 2) * 64;

    wmma::fragment<wmma::accumulator, 16, 16, 16, float> acc[2][4];
#pragma unroll
    for (int i = 0; i < 2; i++)
#pragma unroll
        for (int j = 0; j < 4; j++)
            wmma::fill_fragment(acc[i][j], 0.f);

    const __nv_bfloat16* sAh = (const __nv_bfloat16*)(smem + OFF_AH);
    const __nv_bfloat16* sAl = (const __nv_bfloat16*)(smem + OFF_AL);
    const __nv_bfloat16* sBh = (const __nv_bfloat16*)(smem + OFF_BH);
    const __nv_bfloat16* sBl = (const __nv_bfloat16*)(smem + OFF_BL);

    const int nch = K >> 6;
    for (int ch = 0; ch < nch; ch++) {
        const int kc0 = ch << 6;
        __syncthreads();   // previous iteration's frag loads done before overwrite
        // A: convert 128x64 fp32 -> bf16 hi/lo
#pragma unroll
        for (int it = 0; it < 8; it++) {
            const int idx = tid + it * 256;        // 0..2047
            const int row = idx >> 4;              // 0..127
            const int c4 = (idx & 15) << 2;        // 0..60
            const int r = min(bm + row, M - 1);    // clamp tail; epilogue guards store
            float4 v = *(const float4*)(X + (size_t)r * K + kc0 + c4);
            cvt_storeA(smem, row, c4, v);
        }
        // B: copy preconverted bf16 hi/lo (128x64)
#pragma unroll
        for (int it = 0; it < 4; it++) {
            const int idx = tid + it * 256;        // 0..1023
            const int row = idx >> 3;              // 0..127
            const int c8 = (idx & 7) << 3;         // 0..56
            const size_t g = (size_t)(bn + row) * K + kc0 + c8;
            const size_t so = ((size_t)row * LDS_AB + c8) * 2;
            *(uint4*)(smem + OFF_BH + so) = *(const uint4*)(WH + g);
            *(uint4*)(smem + OFF_BL + so) = *(const uint4*)(WL + g);
        }
        __syncthreads();

#pragma unroll
        for (int ks = 0; ks < 4; ks++) {
            const int k0 = ks * 16;
            wmma::fragment<wmma::matrix_a, 16, 16, 16, __nv_bfloat16, wmma::row_major> ah[2], al[2];
#pragma unroll
            for (int i = 0; i < 2; i++) {
                wmma::load_matrix_sync(ah[i], sAh + (size_t)(wm + 16 * i) * LDS_AB + k0, LDS_AB);
                wmma::load_matrix_sync(al[i], sAl + (size_t)(wm + 16 * i) * LDS_AB + k0, LDS_AB);
            }
#pragma unroll
            for (int j = 0; j < 4; j++) {
                wmma::fragment<wmma::matrix_b, 16, 16, 16, __nv_bfloat16, wmma::col_major> bh, bl;
                wmma::load_matrix_sync(bh, sBh + (size_t)(wn + 16 * j) * LDS_AB + k0, LDS_AB);
                wmma::load_matrix_sync(bl, sBl + (size_t)(wn + 16 * j) * LDS_AB + k0, LDS_AB);
#pragma unroll
                for (int i = 0; i < 2; i++) {
                    wmma::mma_sync(acc[i][j], ah[i], bh, acc[i][j]);
                    wmma::mma_sync(acc[i][j], ah[i], bl, acc[i][j]);
                    wmma::mma_sync(acc[i][j], al[i], bh, acc[i][j]);
                }
            }
        }
    }

    // epilogue: stage fp32 tile in smem, then fused bias/relu/residual store
    __syncthreads();
    float* sC = (float*)smem;
#pragma unroll
    for (int i = 0; i < 2; i++)
#pragma unroll
        for (int j = 0; j < 4; j++)
            wmma::store_matrix_sync(sC + (size_t)(wm + 16 * i) * LDS_C + wn + 16 * j,
                                    acc[i][j], LDS_C, wmma::mem_row_major);
    __syncthreads();

#pragma unroll
    for (int it = 0; it < 16; it++) {
        const int idx = tid + it * 256;            // 0..4095
        const int row = idx >> 5;                  // 0..127
        const int c = (idx & 31) << 2;             // 0..124
        const int m = bm + row;
        if (m < M) {
            const int n = bn + c;
            float4 o = *(const float4*)(sC + (size_t)row * LDS_C + c);
            if (BIAS) {
                float4 b4 = *(const float4*)&bias[n];
                o.x += b4.x; o.y += b4.y; o.z += b4.z; o.w += b4.w;
            }
            if (RELU) {
                o.x = fmaxf(o.x, 0.f); o.y = fmaxf(o.y, 0.f);
                o.z = fmaxf(o.z, 0.f); o.w = fmaxf(o.w, 0.f);
            }
            if (RES) {
                float4 r4 = *(const float4*)&res[(size_t)m * Co + n];
                o.x += r4.x; o.y += r4.y; o.z += r4.z; o.w += r4.w;
            }
            *(float4*)&Y[(size_t)m * Co + n] = o;
        }
    }
}

// ---------------- edge bias: g_eb[e,h] = edge_feat[e,:] . We[h,:] + be[h] ----------------
__global__ void __launch_bounds__(256)
eb_kernel(const float* __restrict__ ef, const float* __restrict__ We,
          const float* __restrict__ be) {
    __shared__ float sWe[HH * EDD];
    __shared__ float sbe[HH];
    for (int i = threadIdx.x; i < HH * EDD; i += 256) sWe[i] = We[i];
    if (threadIdx.x < HH) sbe[threadIdx.x] = be[threadIdx.x];
    __syncthreads();

    const int e = blockIdx.x * 256 + threadIdx.x;  // EE % 256 == 0
    const float4* efp = (const float4*)(ef + (size_t)e * EDD);
    float acc[HH];
#pragma unroll
    for (int h = 0; h < HH; h++) acc[h] = sbe[h];
#pragma unroll
    for (int j4 = 0; j4 < EDD / 4; j4++) {
        float4 v = efp[j4];
#pragma unroll
        for (int h = 0; h < HH; h++) {
            float4 w = *(const float4*)&sWe[h * EDD + j4 * 4];
            acc[h] += v.x * w.x + v.y * w.y + v.z * w.z + v.w * w.w;
        }
    }
    float4 o0 = make_float4(acc[0], acc[1], acc[2], acc[3]);
    float4 o1 = make_float4(acc[4], acc[5], acc[6], acc[7]);
    ((float4*)g_eb)[(size_t)e * 2 + 0] = o0;
    ((float4*)g_eb)[(size_t)e * 2 + 1] = o1;
}

// ---------------- batchnorm stats (column sums / sumsq) ----------------
__global__ void __launch_bounds__(128)
bn_stats_kernel(const float* __restrict__ X, float* __restrict__ sums) {
    const int c = threadIdx.x;  // 128 columns
    const int r0 = blockIdx.x * 256;
    const int rend = min(r0 + 256, NN);
    float s = 0.f, s2 = 0.f;
    for (int r = r0; r < rend; r++) {
        float v = X[(size_t)r * CD + c];
        s += v; s2 += v * v;
    }
    atomicAdd(&sums[c], s);
    atomicAdd(&sums[CD + c], s2);
}

// ---------------- batchnorm apply ----------------
__global__ void __launch_bounds__(256)
bn_apply_kernel(const float* __restrict__ X, float* __restrict__ Y,
                const float* __restrict__ sums,
                const float* __restrict__ g, const float* __restrict__ b) {
    const int i = blockIdx.x * 256 + threadIdx.x;  // NN*CD % 256 == 0
    const int c = i & (CD - 1);
    const float inv = 1.f / (float)NN;
    const float mu = sums[c] * inv;
    const float var = sums[CD + c] * inv - mu * mu;
    const float rs = rsqrtf(var + EPS);
    Y[i] = (X[i] - mu) * rs * g[c] + b[c];
}

// ---------------- launcher ----------------
extern "C" void kernel_launch(void* const* d_in, const int* in_sizes, int n_in,
                              void* d_out, int out_size) {
    const float* q   = (const float*)d_in[0];
    const float* k   = (const float*)d_in[1];
    const float* v   = (const float*)d_in[2];
    const float* ef  = (const float*)d_in[3];
    const int*   src = (const int*)d_in[4];
    const int*   dst = (const int*)d_in[5];
    const float* Wq  = (const float*)d_in[6];
    const float* Wk  = (const float*)d_in[7];
    const float* Wv  = (const float*)d_in[8];
    const float* We  = (const float*)d_in[9];
    const float* be  = (const float*)d_in[10];
    const float* Wo  = (const float*)d_in[11];
    const float* W1  = (const float*)d_in[12];
    const float* b1  = (const float*)d_in[13];
    const float* W2  = (const float*)d_in[14];
    const float* b2  = (const float*)d_in[15];
    const float* g1  = (const float*)d_in[16];
    const float* bt1 = (const float*)d_in[17];
    const float* g2  = (const float*)d_in[18];
    const float* bt2 = (const float*)d_in[19];
    float* out = (float*)d_out;

    float* p_qd; cudaGetSymbolAddress((void**)&p_qd, g_qd);
    float* p_kd; cudaGetSymbolAddress((void**)&p_kd, g_kd);
    float* p_vd; cudaGetSymbolAddress((void**)&p_vd, g_vd);
    float* p_agg; cudaGetSymbolAddress((void**)&p_agg, g_agg);
    float* p_rst; cudaGetSymbolAddress((void**)&p_rst, g_rst);
    float* p_h1; cudaGetSymbolAddress((void**)&p_h1, g_h1);
    float* p_h2; cudaGetSymbolAddress((void**)&p_h2, g_h2);
    float* p_stats; cudaGetSymbolAddress((void**)&p_stats, g_stats);
    __nv_bfloat16* p_wh; cudaGetSymbolAddress((void**)&p_wh, g_wh);
    __nv_bfloat16* p_wl; cudaGetSymbolAddress((void**)&p_wl, g_wl);

    cudaFuncSetAttribute(tc_gemm_kernel<false, false, false>, cudaFuncAttributeMaxDynamicSharedMemorySize, SMEM_TC);
    cudaFuncSetAttribute(tc_gemm_kernel<false, false, true>,  cudaFuncAttributeMaxDynamicSharedMemorySize, SMEM_TC);
    cudaFuncSetAttribute(tc_gemm_kernel<true,  true,  false>, cudaFuncAttributeMaxDynamicSharedMemorySize, SMEM_TC);
    cudaFuncSetAttribute(tc_gemm_kernel<false, true,  true>,  cudaFuncAttributeMaxDynamicSharedMemorySize, SMEM_TC);

    init_kernel<<<(NN + 255) / 256, 256>>>();

    // weight preconversion
    wconv_kernel<<<64, 256>>>(Wq, 16384, WOFF_Q);
    wconv_kernel<<<64, 256>>>(Wk, 16384, WOFF_K);
    wconv_kernel<<<64, 256>>>(Wv, 16384, WOFF_V);
    wconv_kernel<<<64, 256>>>(Wo, 16384, WOFF_O);
    wconv_kernel<<<128, 256>>>(W1, 32768, WOFF_1);
    wconv_kernel<<<128, 256>>>(W2, 32768, WOFF_2);

    const dim3 gC(313, 1);   // ceil(40000/128) x (128/128)
    const dim3 gH(313, 2);   // FFN hidden: 256/128

    // projections (WMMA bf16-split)
    tc_gemm_kernel<false, false, false><<<gC, 256, SMEM_TC>>>(q, p_wh + WOFF_Q, p_wl + WOFF_Q, nullptr, nullptr, p_qd, NN, CD, CD);
    tc_gemm_kernel<false, false, false><<<gC, 256, SMEM_TC>>>(k, p_wh + WOFF_K, p_wl + WOFF_K, nullptr, nullptr, p_kd, NN, CD, CD);
    tc_gemm_kernel<false, false, false><<<gC, 256, SMEM_TC>>>(v, p_wh + WOFF_V, p_wl + WOFF_V, nullptr, nullptr, p_vd, NN, CD, CD);

    // edge phase: bias, CSR build, fused attention
    eb_kernel<<<EE / 256, 256>>>(ef, We, be);
    hist_kernel<<<EE / 256, 256>>>(dst);
    scan_kernel<<<1, 1024>>>();
    scatter_kernel<<<EE / 256, 256>>>(src, dst);
    attn_kernel<<<NN / 8, 256>>>();

    // out proj + residual, BN1
    tc_gemm_kernel<false, false, true><<<gC, 256, SMEM_TC>>>(p_agg, p_wh + WOFF_O, p_wl + WOFF_O, nullptr, q, p_rst, NN, CD, CD);
    bn_stats_kernel<<<(NN + 255) / 256, 128>>>(p_rst, p_stats);
    bn_apply_kernel<<<NN * CD / 256, 256>>>(p_rst, p_rst, p_stats, g1, bt1);

    // FFN + residual, BN2
    tc_gemm_kernel<true, true, false><<<gH, 256, SMEM_TC>>>(p_rst, p_wh + WOFF_1, p_wl + WOFF_1, b1, nullptr, p_h1, NN, CD, C2);
    tc_gemm_kernel<false, true, true><<<gC, 256, SMEM_TC>>>(p_h1, p_wh + WOFF_2, p_wl + WOFF_2, b2, p_rst, p_h2, NN, C2, CD);
    bn_stats_kernel<<<(NN + 255) / 256, 128>>>(p_h2, p_stats + 2 * CD);
    bn_apply_kernel<<<NN * CD / 256, 256>>>(p_h2, out, p_stats + 2 * CD, g2, bt2);
}

// round 8
// speedup vs baseline: 1.6583x; 1.1129x over previous
#include <cuda_runtime.h>
#include <cuda_bf16.h>
#include <mma.h>
#include <cstdint>

using namespace nvcuda;

// ---------------- problem constants ----------------
#define NN 40000      // nodes
#define EE 640000     // edges
#define CD 128        // channels (= IN = H*D)
#define HH 8          // heads
#define DD 16         // dim per head
#define EDD 64        // edge feature dim
#define C2 256        // FFN hidden
#define EPS 1e-5f

// ---------------- scratch (static device globals; no allocs allowed) ----------------
__device__ float    g_qd[(size_t)NN * CD];
__device__ float    g_kd[(size_t)NN * CD];
__device__ float    g_vd[(size_t)NN * CD];
__device__ float    g_eb[(size_t)EE * HH];    // per-edge bias
__device__ float    g_agg[(size_t)NN * CD];
__device__ float    g_rst[(size_t)NN * CD];
__device__ float    g_h1[(size_t)NN * C2];
__device__ float    g_h2[(size_t)NN * CD];
__device__ float    g_stats[4 * CD];          // [sum1, sq1, sum2, sq2]
__device__ float    g_coef[4 * CD];           // [scale1, shift1, scale2, shift2]
// CSR
__device__ int      g_cnt[NN];
__device__ int      g_pos[NN];
__device__ int      g_row[NN + 1];
__device__ int      g_esrc[EE];
__device__ int      g_eid[EE];
// preconverted weights (bf16 hi/lo)
#define WOFF_Q  0
#define WOFF_K  16384
#define WOFF_V  32768
#define WOFF_O  49152
#define WOFF_1  65536
#define WOFF_2  98304
#define WTOT    131072
__device__ __nv_bfloat16 g_wh[WTOT];
__device__ __nv_bfloat16 g_wl[WTOT];

// ---------------- init: zero counters every call (graph replays!) ----------------
__global__ void init_kernel() {
    int i = blockIdx.x * blockDim.x + threadIdx.x;
    if (i < NN) { g_cnt[i] = 0; g_pos[i] = 0; }
    if (i < 4 * CD) g_stats[i] = 0.f;
}

// ---------------- weight preconversion fp32 -> bf16 hi/lo (one launch) ----------------
__global__ void wconv_all_kernel(const float* __restrict__ Wq, const float* __restrict__ Wk,
                                 const float* __restrict__ Wv, const float* __restrict__ Wo,
                                 const float* __restrict__ W1, const float* __restrict__ W2) {
    int i = blockIdx.x * 256 + threadIdx.x;   // WTOT % 256 == 0
    const float* src; int off;
    if (i < WOFF_K)      { src = Wq; off = i - WOFF_Q; }
    else if (i < WOFF_V) { src = Wk; off = i - WOFF_K; }
    else if (i < WOFF_O) { src = Wv; off = i - WOFF_V; }
    else if (i < WOFF_1) { src = Wo; off = i - WOFF_O; }
    else if (i < WOFF_2) { src = W1; off = i - WOFF_1; }
    else                 { src = W2; off = i - WOFF_2; }
    float v = src[off];
    __nv_bfloat16 h = __float2bfloat16(v);
    g_wh[i] = h;
    g_wl[i] = __float2bfloat16(v - __bfloat162float(h));
}

// ---------------- CSR build ----------------
__global__ void __launch_bounds__(1024)
scan_kernel() {
    __shared__ int sdata[1024];
    const int t = threadIdx.x;
    int carry = 0;
    for (int base = 0; base < NN; base += 1024) {
        int x = (base + t < NN) ? g_cnt[base + t] : 0;
        sdata[t] = x;
        __syncthreads();
#pragma unroll
        for (int off = 1; off < 1024; off <<= 1) {
            int v = (t >= off) ? sdata[t - off] : 0;
            __syncthreads();
            sdata[t] += v;
            __syncthreads();
        }
        if (base + t < NN) g_row[base + t] = carry + sdata[t] - x;
        carry += sdata[1023];
        __syncthreads();
    }
    if (t == 0) g_row[NN] = EE;
}

__global__ void scatter_kernel(const int* __restrict__ src, const int* __restrict__ dst) {
    int e = blockIdx.x * 256 + threadIdx.x;
    const int d = dst[e];
    int p = atomicAdd(&g_pos[d], 1);
    int o = g_row[d] + p;
    g_esrc[o] = src[e];
    g_eid[o] = e;
}

// ---------------- fused one-pass attention (warp per node, online softmax) ----------------
__global__ void __launch_bounds__(256)
attn_kernel() {
    const int warpId = (blockIdx.x * 256 + threadIdx.x) >> 5;
    const int lane = threadIdx.x & 31;
    if (warpId >= NN) return;
    const int n = warpId;
    const int r0 = g_row[n], r1 = g_row[n + 1];
    const int h = lane >> 2;

    float4 qv = ((const float4*)g_qd)[(size_t)n * 32 + lane];

    float m = -3.0e38f, den = 0.f;
    float4 acc = make_float4(0.f, 0.f, 0.f, 0.f);
    for (int i = r0; i < r1; i++) {
        const int s = g_esrc[i];
        const int e = g_eid[i];
        float4 kv = ((const float4*)g_kd)[(size_t)s * 32 + lane];
        float p = qv.x * kv.x + qv.y * kv.y + qv.z * kv.z + qv.w * kv.w;
        p += __shfl_xor_sync(0xffffffffu, p, 1);
        p += __shfl_xor_sync(0xffffffffu, p, 2);
        const float sc = p * 0.25f + __ldg(&g_eb[(size_t)e * HH + h]);  // 1/sqrt(16)
        const float nm = fmaxf(m, sc);
        const float corr = __expf(m - nm);   // first iter: exp(-inf) = 0
        const float w = __expf(sc - nm);
        m = nm;
        den = den * corr + w;
        float4 vv = ((const float4*)g_vd)[(size_t)s * 32 + lane];
        acc.x = acc.x * corr + w * vv.x;
        acc.y = acc.y * corr + w * vv.y;
        acc.z = acc.z * corr + w * vv.z;
        acc.w = acc.w * corr + w * vv.w;
    }
    const float inv = (den > 0.f) ? (1.f / den) : 0.f;
    acc.x *= inv; acc.y *= inv; acc.z *= inv; acc.w *= inv;
    ((float4*)g_agg)[(size_t)n * 32 + lane] = acc;
}

// ---------------- WMMA bf16-split GEMM with fused BN options ----------------
#define LDS_AB 72
#define OFF_AH 0
#define OFF_AL (OFF_AH + 128 * LDS_AB * 2)
#define OFF_BH (OFF_AL + 128 * LDS_AB * 2)
#define OFF_BL (OFF_BH + 128 * LDS_AB * 2)
#define SMEM_TC (OFF_BL + 128 * LDS_AB * 2)  // 73728 bytes
#define LDS_C 132

__device__ __forceinline__ void cvt_storeA(char* smem, int row, int c4, float4 v) {
    __nv_bfloat162 h0 = __floats2bfloat162_rn(v.x, v.y);
    __nv_bfloat162 h1 = __floats2bfloat162_rn(v.z, v.w);
    float2 f0 = __bfloat1622float2(h0);
    float2 f1 = __bfloat1622float2(h1);
    __nv_bfloat162 l0 = __floats2bfloat162_rn(v.x - f0.x, v.y - f0.y);
    __nv_bfloat162 l1 = __floats2bfloat162_rn(v.z - f1.x, v.w - f1.y);
    uint2 ph, pl;
    ph.x = *(uint32_t*)&h0; ph.y = *(uint32_t*)&h1;
    pl.x = *(uint32_t*)&l0; pl.y = *(uint32_t*)&l1;
    *(uint2*)(smem + OFF_AH + ((size_t)row * LDS_AB + c4) * 2) = ph;
    *(uint2*)(smem + OFF_AL + ((size_t)row * LDS_AB + c4) * 2) = pl;
}

// BNIN: A-load applies x*coefA[c] + coefA[128+c].  RESBN: residual likewise via coefR.
// STATS: epilogue accumulates column sum/sumsq of Y into stats[0..127],[128..255].
template <bool RELU, bool BIAS, bool RES, bool BNIN, bool RESBN, bool STATS>
__global__ void __launch_bounds__(256, 2)
tc_gemm_kernel(const float* __restrict__ X,
               const __nv_bfloat16* __restrict__ WH, const __nv_bfloat16* __restrict__ WL,
               const float* __restrict__ bias, const float* __restrict__ res,
               const float* __restrict__ coefA, const float* __restrict__ coefR,
               float* __restrict__ stats,
               float* __restrict__ Y, int M, int K, int Co) {
    extern __shared__ char smem[];
    const int tid = threadIdx.x;
    const int warp = tid >> 5;
    const int bm = blockIdx.x * 128;
    const int bn = blockIdx.y * 128;
    const int wm = (warp & 3) * 32;
    const int wn = (warp >> 2) * 64;

    wmma::fragment<wmma::accumulator, 16, 16, 16, float> acc[2][4];
#pragma unroll
    for (int i = 0; i < 2; i++)
#pragma unroll
        for (int j = 0; j < 4; j++)
            wmma::fill_fragment(acc[i][j], 0.f);

    const __nv_bfloat16* sAh = (const __nv_bfloat16*)(smem + OFF_AH);
    const __nv_bfloat16* sAl = (const __nv_bfloat16*)(smem + OFF_AL);
    const __nv_bfloat16* sBh = (const __nv_bfloat16*)(smem + OFF_BH);
    const __nv_bfloat16* sBl = (const __nv_bfloat16*)(smem + OFF_BL);

    const int nch = K >> 6;
    for (int ch = 0; ch < nch; ch++) {
        const int kc0 = ch << 6;
        __syncthreads();
        // A: convert 128x64 fp32 -> bf16 hi/lo (optionally BN-normalized)
#pragma unroll
        for (int it = 0; it < 8; it++) {
            const int idx = tid + it * 256;
            const int row = idx >> 4;
            const int c4 = (idx & 15) << 2;
            const int r = min(bm + row, M - 1);
            float4 v = *(const float4*)(X + (size_t)r * K + kc0 + c4);
            if (BNIN) {
                const int c = kc0 + c4;
                float4 s4 = *(const float4*)(coefA + c);
                float4 t4 = *(const float4*)(coefA + 128 + c);
                v.x = v.x * s4.x + t4.x; v.y = v.y * s4.y + t4.y;
                v.z = v.z * s4.z + t4.z; v.w = v.w * s4.w + t4.w;
            }
            cvt_storeA(smem, row, c4, v);
        }
        // B: copy preconverted bf16 hi/lo
#pragma unroll
        for (int it = 0; it < 4; it++) {
            const int idx = tid + it * 256;
            const int row = idx >> 3;
            const int c8 = (idx & 7) << 3;
            const size_t g = (size_t)(bn + row) * K + kc0 + c8;
            const size_t so = ((size_t)row * LDS_AB + c8) * 2;
            *(uint4*)(smem + OFF_BH + so) = *(const uint4*)(WH + g);
            *(uint4*)(smem + OFF_BL + so) = *(const uint4*)(WL + g);
        }
        __syncthreads();

#pragma unroll
        for (int ks = 0; ks < 4; ks++) {
            const int k0 = ks * 16;
            wmma::fragment<wmma::matrix_a, 16, 16, 16, __nv_bfloat16, wmma::row_major> ah[2], al[2];
#pragma unroll
            for (int i = 0; i < 2; i++) {
                wmma::load_matrix_sync(ah[i], sAh + (size_t)(wm + 16 * i) * LDS_AB + k0, LDS_AB);
                wmma::load_matrix_sync(al[i], sAl + (size_t)(wm + 16 * i) * LDS_AB + k0, LDS_AB);
            }
#pragma unroll
            for (int j = 0; j < 4; j++) {
                wmma::fragment<wmma::matrix_b, 16, 16, 16, __nv_bfloat16, wmma::col_major> bh, bl;
                wmma::load_matrix_sync(bh, sBh + (size_t)(wn + 16 * j) * LDS_AB + k0, LDS_AB);
                wmma::load_matrix_sync(bl, sBl + (size_t)(wn + 16 * j) * LDS_AB + k0, LDS_AB);
#pragma unroll
                for (int i = 0; i < 2; i++) {
                    wmma::mma_sync(acc[i][j], ah[i], bh, acc[i][j]);
                    wmma::mma_sync(acc[i][j], ah[i], bl, acc[i][j]);
                    wmma::mma_sync(acc[i][j], al[i], bh, acc[i][j]);
                }
            }
        }
    }

    // epilogue: stage fp32 tile in smem, fused bias/relu/residual store (+ stats)
    __syncthreads();
    float* sC = (float*)smem;
#pragma unroll
    for (int i = 0; i < 2; i++)
#pragma unroll
        for (int j = 0; j < 4; j++)
            wmma::store_matrix_sync(sC + (size_t)(wm + 16 * i) * LDS_C + wn + 16 * j,
                                    acc[i][j], LDS_C, wmma::mem_row_major);
    __syncthreads();

    float st_s[4] = {0.f, 0.f, 0.f, 0.f};
    float st_q[4] = {0.f, 0.f, 0.f, 0.f};
#pragma unroll
    for (int it = 0; it < 16; it++) {
        const int idx = tid + it * 256;
        const int row = idx >> 5;
        const int c = (idx & 31) << 2;   // == (tid&31)*4, constant per thread
        const int m = bm + row;
        if (m < M) {
            const int n = bn + c;
            float4 o = *(const float4*)(sC + (size_t)row * LDS_C + c);
            if (BIAS) {
                float4 b4 = *(const float4*)&bias[n];
                o.x += b4.x; o.y += b4.y; o.z += b4.z; o.w += b4.w;
            }
            if (RELU) {
                o.x = fmaxf(o.x, 0.f); o.y = fmaxf(o.y, 0.f);
                o.z = fmaxf(o.z, 0.f); o.w = fmaxf(o.w, 0.f);
            }
            if (RES) {
                float4 r4 = *(const float4*)&res[(size_t)m * Co + n];
                if (RESBN) {
                    float4 s4 = *(const float4*)(coefR + c);
                    float4 t4 = *(const float4*)(coefR + 128 + c);
                    r4.x = r4.x * s4.x + t4.x; r4.y = r4.y * s4.y + t4.y;
                    r4.z = r4.z * s4.z + t4.z; r4.w = r4.w * s4.w + t4.w;
                }
                o.x += r4.x; o.y += r4.y; o.z += r4.z; o.w += r4.w;
            }
            *(float4*)&Y[(size_t)m * Co + n] = o;
            if (STATS) {
                st_s[0] += o.x; st_s[1] += o.y; st_s[2] += o.z; st_s[3] += o.w;
                st_q[0] += o.x * o.x; st_q[1] += o.y * o.y;
                st_q[2] += o.z * o.z; st_q[3] += o.w * o.w;
            }
        }
    }
    if (STATS) {
        __syncthreads();
        float* sP = (float*)smem;   // 256 threads x 8 floats
#pragma unroll
        for (int j = 0; j < 4; j++) { sP[tid * 8 + j] = st_s[j]; sP[tid * 8 + 4 + j] = st_q[j]; }
        __syncthreads();
        if (tid < 128) {
            const int cg = tid >> 2, sub = tid & 3;
            float s = 0.f, qq = 0.f;
#pragma unroll
            for (int rg = 0; rg < 8; rg++) {
                const int tt = rg * 32 + cg;
                s += sP[tt * 8 + sub];
                qq += sP[tt * 8 + 4 + sub];
            }
            atomicAdd(&stats[bn + tid], s);
            atomicAdd(&stats[128 + bn + tid], qq);
        }
    }
}

// ---------------- edge bias + dst histogram (fused) ----------------
__global__ void __launch_bounds__(256)
eb_kernel(const float* __restrict__ ef, const float* __restrict__ We,
          const float* __restrict__ be, const int* __restrict__ dst) {
    __shared__ float sWe[HH * EDD];
    __shared__ float sbe[HH];
    for (int i = threadIdx.x; i < HH * EDD; i += 256) sWe[i] = We[i];
    if (threadIdx.x < HH) sbe[threadIdx.x] = be[threadIdx.x];
    __syncthreads();

    const int e = blockIdx.x * 256 + threadIdx.x;  // EE % 256 == 0
    atomicAdd(&g_cnt[dst[e]], 1);
    const float4* efp = (const float4*)(ef + (size_t)e * EDD);
    float acc[HH];
#pragma unroll
    for (int h = 0; h < HH; h++) acc[h] = sbe[h];
#pragma unroll
    for (int j4 = 0; j4 < EDD / 4; j4++) {
        float4 v = efp[j4];
#pragma unroll
        for (int h = 0; h < HH; h++) {
            float4 w = *(const float4*)&sWe[h * EDD + j4 * 4];
            acc[h] += v.x * w.x + v.y * w.y + v.z * w.z + v.w * w.w;
        }
    }
    float4 o0 = make_float4(acc[0], acc[1], acc[2], acc[3]);
    float4 o1 = make_float4(acc[4], acc[5], acc[6], acc[7]);
    ((float4*)g_eb)[(size_t)e * 2 + 0] = o0;
    ((float4*)g_eb)[(size_t)e * 2 + 1] = o1;
}

// ---------------- BN coefficients from stats ----------------
__global__ void bn_coef_kernel(const float* __restrict__ sums,
                               const float* __restrict__ g, const float* __restrict__ b,
                               float* __restrict__ coef) {
    const int c = threadIdx.x;  // 128
    const float inv = 1.f / (float)NN;
    const float mu = sums[c] * inv;
    const float var = sums[128 + c] * inv - mu * mu;
    const float rs = rsqrtf(var + EPS);
    const float sc = rs * g[c];
    coef[c] = sc;
    coef[128 + c] = b[c] - mu * sc;
}

// ---------------- final apply: out = x*scale + shift ----------------
__global__ void __launch_bounds__(256)
bn_apply_kernel(const float* __restrict__ X, float* __restrict__ Y,
                const float* __restrict__ coef) {
    const int i = blockIdx.x * 256 + threadIdx.x;  // NN*CD % 256 == 0
    const int c = i & (CD - 1);
    Y[i] = X[i] * coef[c] + coef[128 + c];
}

// ---------------- launcher ----------------
extern "C" void kernel_launch(void* const* d_in, const int* in_sizes, int n_in,
                              void* d_out, int out_size) {
    const float* q   = (const float*)d_in[0];
    const float* k   = (const float*)d_in[1];
    const float* v   = (const float*)d_in[2];
    const float* ef  = (const float*)d_in[3];
    const int*   src = (const int*)d_in[4];
    const int*   dst = (const int*)d_in[5];
    const float* Wq  = (const float*)d_in[6];
    const float* Wk  = (const float*)d_in[7];
    const float* Wv  = (const float*)d_in[8];
    const float* We  = (const float*)d_in[9];
    const float* be  = (const float*)d_in[10];
    const float* Wo  = (const float*)d_in[11];
    const float* W1  = (const float*)d_in[12];
    const float* b1  = (const float*)d_in[13];
    const float* W2  = (const float*)d_in[14];
    const float* b2  = (const float*)d_in[15];
    const float* g1  = (const float*)d_in[16];
    const float* bt1 = (const float*)d_in[17];
    const float* g2  = (const float*)d_in[18];
    const float* bt2 = (const float*)d_in[19];
    float* out = (float*)d_out;

    float* p_qd; cudaGetSymbolAddress((void**)&p_qd, g_qd);
    float* p_kd; cudaGetSymbolAddress((void**)&p_kd, g_kd);
    float* p_vd; cudaGetSymbolAddress((void**)&p_vd, g_vd);
    float* p_agg; cudaGetSymbolAddress((void**)&p_agg, g_agg);
    float* p_rst; cudaGetSymbolAddress((void**)&p_rst, g_rst);
    float* p_h1; cudaGetSymbolAddress((void**)&p_h1, g_h1);
    float* p_h2; cudaGetSymbolAddress((void**)&p_h2, g_h2);
    float* p_stats; cudaGetSymbolAddress((void**)&p_stats, g_stats);
    float* p_coef; cudaGetSymbolAddress((void**)&p_coef, g_coef);
    __nv_bfloat16* p_wh; cudaGetSymbolAddress((void**)&p_wh, g_wh);
    __nv_bfloat16* p_wl; cudaGetSymbolAddress((void**)&p_wl, g_wl);

    cudaFuncSetAttribute(tc_gemm_kernel<false, false, false, false, false, false>, cudaFuncAttributeMaxDynamicSharedMemorySize, SMEM_TC);
    cudaFuncSetAttribute(tc_gemm_kernel<false, false, true,  false, false, true >, cudaFuncAttributeMaxDynamicSharedMemorySize, SMEM_TC);
    cudaFuncSetAttribute(tc_gemm_kernel<true,  true,  false, true,  false, false>, cudaFuncAttributeMaxDynamicSharedMemorySize, SMEM_TC);
    cudaFuncSetAttribute(tc_gemm_kernel<false, true,  true,  false, true,  true >, cudaFuncAttributeMaxDynamicSharedMemorySize, SMEM_TC);

    init_kernel<<<(NN + 255) / 256, 256>>>();
    wconv_all_kernel<<<WTOT / 256, 256>>>(Wq, Wk, Wv, Wo, W1, W2);

    const dim3 gC(313, 1);
    const dim3 gH(313, 2);

    // projections
    tc_gemm_kernel<false, false, false, false, false, false><<<gC, 256, SMEM_TC>>>(
        q, p_wh + WOFF_Q, p_wl + WOFF_Q, nullptr, nullptr, nullptr, nullptr, nullptr, p_qd, NN, CD, CD);
    tc_gemm_kernel<false, false, false, false, false, false><<<gC, 256, SMEM_TC>>>(
        k, p_wh + WOFF_K, p_wl + WOFF_K, nullptr, nullptr, nullptr, nullptr, nullptr, p_kd, NN, CD, CD);
    tc_gemm_kernel<false, false, false, false, false, false><<<gC, 256, SMEM_TC>>>(
        v, p_wh + WOFF_V, p_wl + WOFF_V, nullptr, nullptr, nullptr, nullptr, nullptr, p_vd, NN, CD, CD);

    // edge phase
    eb_kernel<<<EE / 256, 256>>>(ef, We, be, dst);
    scan_kernel<<<1, 1024>>>();
    scatter_kernel<<<EE / 256, 256>>>(src, dst);
    attn_kernel<<<NN / 8, 256>>>();

    // out proj + residual, stats for BN1 fused in epilogue
    tc_gemm_kernel<false, false, true, false, false, true><<<gC, 256, SMEM_TC>>>(
        p_agg, p_wh + WOFF_O, p_wl + WOFF_O, nullptr, q, nullptr, nullptr, p_stats, p_rst, NN, CD, CD);
    bn_coef_kernel<<<1, 128>>>(p_stats, g1, bt1, p_coef);

    // FFN: W1 applies BN1 on A-load; W2 adds BN1(rst) residual + emits stats for BN2
    tc_gemm_kernel<true, true, false, true, false, false><<<gH, 256, SMEM_TC>>>(
        p_rst, p_wh + WOFF_1, p_wl + WOFF_1, b1, nullptr, p_coef, nullptr, nullptr, p_h1, NN, CD, C2);
    tc_gemm_kernel<false, true, true, false, true, true><<<gC, 256, SMEM_TC>>>(
        p_h1, p_wh + WOFF_2, p_wl + WOFF_2, b2, p_rst, nullptr, p_coef, p_stats + 2 * CD, p_h2, NN, C2, CD);
    bn_coef_kernel<<<1, 128>>>(p_stats + 2 * CD, g2, bt2, p_coef + 2 * CD);
    bn_apply_kernel<<<NN * CD / 256, 256>>>(p_h2, out, p_coef + 2 * CD);
}

// round 9
// speedup vs baseline: 1.8915x; 1.1407x over previous
#include <cuda_runtime.h>
#include <cuda_bf16.h>
#include <mma.h>
#include <cstdint>

using namespace nvcuda;

// ---------------- problem constants ----------------
#define NN 40000      // nodes
#define EE 640000     // edges
#define CD 128        // channels (= IN = H*D)
#define HH 8          // heads
#define DD 16         // dim per head
#define EDD 64        // edge feature dim
#define C2 256        // FFN hidden
#define EPS 1e-5f

// ---------------- scratch (static device globals; no allocs allowed) ----------------
__device__ float    g_qd[(size_t)NN * CD];
__device__ float    g_kd[(size_t)NN * CD];
__device__ float    g_vd[(size_t)NN * CD];
__device__ float    g_eb[(size_t)EE * HH];
__device__ float    g_agg[(size_t)NN * CD];
__device__ float    g_rst[(size_t)NN * CD];
__device__ float    g_h1[(size_t)NN * C2];
__device__ float    g_h2[(size_t)NN * CD];
__device__ float    g_stats[4 * CD];
__device__ float    g_coef[4 * CD];
// CSR
__device__ int      g_cnt[NN];
__device__ int      g_pos[NN];
__device__ int      g_row[NN + 1];
__device__ int      g_esrc[EE];
__device__ int      g_eid[EE];
// preconverted weights (bf16 hi/lo)
#define WOFF_Q  0
#define WOFF_K  16384
#define WOFF_V  32768
#define WOFF_O  49152
#define WOFF_1  65536
#define WOFF_2  98304
#define WTOT    131072
__device__ __align__(16) __nv_bfloat16 g_wh[WTOT];
__device__ __align__(16) __nv_bfloat16 g_wl[WTOT];

// ---------------- cp.async helpers ----------------
__device__ __forceinline__ void cp_async16(uint32_t saddr, const void* gaddr) {
    asm volatile("cp.async.ca.shared.global [%0], [%1], 16;" :: "r"(saddr), "l"(gaddr));
}
#define CP_COMMIT() asm volatile("cp.async.commit_group;" ::: "memory")
#define CP_WAIT0()  asm volatile("cp.async.wait_group 0;" ::: "memory")

// ---------------- init + weight preconversion (single launch) ----------------
__global__ void initconv_kernel(const float* __restrict__ Wq, const float* __restrict__ Wk,
                                const float* __restrict__ Wv, const float* __restrict__ Wo,
                                const float* __restrict__ W1, const float* __restrict__ W2) {
    int i = blockIdx.x * 256 + threadIdx.x;   // WTOT/256 = 512 blocks
    if (i < NN) { g_cnt[i] = 0; g_pos[i] = 0; }
    if (i < 4 * CD) g_stats[i] = 0.f;
    if (i < WTOT) {
        const float* src; int off;
        if (i < WOFF_K)      { src = Wq; off = i - WOFF_Q; }
        else if (i < WOFF_V) { src = Wk; off = i - WOFF_K; }
        else if (i < WOFF_O) { src = Wv; off = i - WOFF_V; }
        else if (i < WOFF_1) { src = Wo; off = i - WOFF_O; }
        else if (i < WOFF_2) { src = W1; off = i - WOFF_1; }
        else                 { src = W2; off = i - WOFF_2; }
        float v = src[off];
        __nv_bfloat16 h = __float2bfloat16(v);
        g_wh[i] = h;
        g_wl[i] = __float2bfloat16(v - __bfloat162float(h));
    }
}

// ---------------- CSR build: warp-shuffle scan ----------------
__global__ void __launch_bounds__(1024)
scan_kernel() {
    __shared__ int wsum[32];
    const int t = threadIdx.x, lane = t & 31, wid = t >> 5;
    int carry = 0;
    for (int base = 0; base < NN; base += 1024) {
        const int idx = base + t;
        int x = (idx < NN) ? g_cnt[idx] : 0;
        int v = x;
#pragma unroll
        for (int o = 1; o < 32; o <<= 1) {
            int u = __shfl_up_sync(0xffffffffu, v, o);
            if (lane >= o) v += u;
        }
        if (lane == 31) wsum[wid] = v;
        __syncthreads();
        if (wid == 0) {
            int w = wsum[lane];
#pragma unroll
            for (int o = 1; o < 32; o <<= 1) {
                int u = __shfl_up_sync(0xffffffffu, w, o);
                if (lane >= o) w += u;
            }
            wsum[lane] = w;
        }
        __syncthreads();
        const int off = carry + (wid > 0 ? wsum[wid - 1] : 0);
        if (idx < NN) g_row[idx] = off + v - x;
        carry += wsum[31];
        __syncthreads();
    }
    if (t == 0) g_row[NN] = EE;
}

__global__ void scatter_kernel(const int* __restrict__ src, const int* __restrict__ dst) {
    int e = blockIdx.x * 256 + threadIdx.x;
    const int d = dst[e];
    int p = atomicAdd(&g_pos[d], 1);
    int o = g_row[d] + p;
    g_esrc[o] = src[e];
    g_eid[o] = e;
}

// ---------------- fused one-pass attention (warp per node, pipelined) ----------------
__global__ void __launch_bounds__(256)
attn_kernel() {
    const int warpId = (blockIdx.x * 256 + threadIdx.x) >> 5;
    const int lane = threadIdx.x & 31;
    if (warpId >= NN) return;
    const int n = warpId;
    const int r0 = g_row[n], r1 = g_row[n + 1];
    const int h = lane >> 2;

    float4 qv = ((const float4*)g_qd)[(size_t)n * 32 + lane];

    float m = -3.0e38f, den = 0.f;
    float4 acc = make_float4(0.f, 0.f, 0.f, 0.f);
    if (r0 < r1) {
        int s = g_esrc[r0];
        int e = g_eid[r0];
        float4 kv = ((const float4*)g_kd)[(size_t)s * 32 + lane];
        float4 vv = ((const float4*)g_vd)[(size_t)s * 32 + lane];
        float ebv = __ldg(&g_eb[(size_t)e * HH + h]);
        for (int i = r0; i < r1; i++) {
            // prefetch next edge
            float4 nkv = kv, nvv = vv;
            float nebv = 0.f;
            if (i + 1 < r1) {
                const int ns = g_esrc[i + 1];
                const int ne = g_eid[i + 1];
                nkv = ((const float4*)g_kd)[(size_t)ns * 32 + lane];
                nvv = ((const float4*)g_vd)[(size_t)ns * 32 + lane];
                nebv = __ldg(&g_eb[(size_t)ne * HH + h]);
            }
            // compute current
            float p = qv.x * kv.x + qv.y * kv.y + qv.z * kv.z + qv.w * kv.w;
            p += __shfl_xor_sync(0xffffffffu, p, 1);
            p += __shfl_xor_sync(0xffffffffu, p, 2);
            const float sc = p * 0.25f + ebv;
            const float nm = fmaxf(m, sc);
            const float corr = __expf(m - nm);
            const float w = __expf(sc - nm);
            m = nm;
            den = den * corr + w;
            acc.x = acc.x * corr + w * vv.x;
            acc.y = acc.y * corr + w * vv.y;
            acc.z = acc.z * corr + w * vv.z;
            acc.w = acc.w * corr + w * vv.w;
            kv = nkv; vv = nvv; ebv = nebv;
        }
    }
    const float inv = (den > 0.f) ? (1.f / den) : 0.f;
    acc.x *= inv; acc.y *= inv; acc.z *= inv; acc.w *= inv;
    ((float4*)g_agg)[(size_t)n * 32 + lane] = acc;
}

// ---------------- WMMA bf16-split GEMM core ----------------
#define LDS_AB 72
#define OFF_AH 0
#define OFF_AL (OFF_AH + 128 * LDS_AB * 2)
#define OFF_BH (OFF_AL + 128 * LDS_AB * 2)
#define OFF_BL (OFF_BH + 128 * LDS_AB * 2)
#define SMEM_TC (OFF_BL + 128 * LDS_AB * 2)  // 73728 bytes
#define LDS_C 132

__device__ __forceinline__ void cvt_storeA(char* smem, int row, int c4, float4 v) {
    __nv_bfloat162 h0 = __floats2bfloat162_rn(v.x, v.y);
    __nv_bfloat162 h1 = __floats2bfloat162_rn(v.z, v.w);
    float2 f0 = __bfloat1622float2(h0);
    float2 f1 = __bfloat1622float2(h1);
    __nv_bfloat162 l0 = __floats2bfloat162_rn(v.x - f0.x, v.y - f0.y);
    __nv_bfloat162 l1 = __floats2bfloat162_rn(v.z - f1.x, v.w - f1.y);
    uint2 ph, pl;
    ph.x = *(uint32_t*)&h0; ph.y = *(uint32_t*)&h1;
    pl.x = *(uint32_t*)&l0; pl.y = *(uint32_t*)&l1;
    *(uint2*)(smem + OFF_AH + ((size_t)row * LDS_AB + c4) * 2) = ph;
    *(uint2*)(smem + OFF_AL + ((size_t)row * LDS_AB + c4) * 2) = pl;
}

template <bool RELU, bool BIAS, bool RES, bool BNIN, bool RESBN, bool STATS>
__device__ __forceinline__ void gemm_core(
    const float* __restrict__ X,
    const __nv_bfloat16* __restrict__ WH, const __nv_bfloat16* __restrict__ WL,
    const float* __restrict__ bias, const float* __restrict__ res,
    const float* __restrict__ coefA, const float* __restrict__ coefR,
    float* __restrict__ stats, float* __restrict__ Y,
    int M, int K, int Co, int bm, int bn, char* smem) {
    const int tid = threadIdx.x;
    const int warp = tid >> 5;
    const int wm = (warp & 3) * 32;
    const int wn = (warp >> 2) * 64;
    const uint32_t sb = (uint32_t)__cvta_generic_to_shared(smem);

    wmma::fragment<wmma::accumulator, 16, 16, 16, float> acc[2][4];
#pragma unroll
    for (int i = 0; i < 2; i++)
#pragma unroll
        for (int j = 0; j < 4; j++)
            wmma::fill_fragment(acc[i][j], 0.f);

    const __nv_bfloat16* sAh = (const __nv_bfloat16*)(smem + OFF_AH);
    const __nv_bfloat16* sAl = (const __nv_bfloat16*)(smem + OFF_AL);
    const __nv_bfloat16* sBh = (const __nv_bfloat16*)(smem + OFF_BH);
    const __nv_bfloat16* sBl = (const __nv_bfloat16*)(smem + OFF_BL);

    const int nch = K >> 6;
    for (int ch = 0; ch < nch; ch++) {
        const int kc0 = ch << 6;
        __syncthreads();   // all warps done reading prev chunk smem
        // B: async copy of preconverted bf16 hi/lo (overlaps with A conversion)
#pragma unroll
        for (int it = 0; it < 4; it++) {
            const int idx = tid + it * 256;
            const int row = idx >> 3;
            const int c8 = (idx & 7) << 3;
            const size_t g = (size_t)(bn + row) * K + kc0 + c8;
            const uint32_t so = sb + OFF_BH + (uint32_t)(row * LDS_AB + c8) * 2;
            cp_async16(so, WH + g);
            cp_async16(so + (OFF_BL - OFF_BH), WL + g);
        }
        CP_COMMIT();
        // A: convert 128x64 fp32 -> bf16 hi/lo (optionally BN-normalized)
#pragma unroll
        for (int it = 0; it < 8; it++) {
            const int idx = tid + it * 256;
            const int row = idx >> 4;
            const int c4 = (idx & 15) << 2;
            const int r = min(bm + row, M - 1);
            float4 v = *(const float4*)(X + (size_t)r * K + kc0 + c4);
            if (BNIN) {
                const int c = kc0 + c4;
                float4 s4 = *(const float4*)(coefA + c);
                float4 t4 = *(const float4*)(coefA + 128 + c);
                v.x = v.x * s4.x + t4.x; v.y = v.y * s4.y + t4.y;
                v.z = v.z * s4.z + t4.z; v.w = v.w * s4.w + t4.w;
            }
            cvt_storeA(smem, row, c4, v);
        }
        CP_WAIT0();
        __syncthreads();

#pragma unroll
        for (int ks = 0; ks < 4; ks++) {
            const int k0 = ks * 16;
            wmma::fragment<wmma::matrix_a, 16, 16, 16, __nv_bfloat16, wmma::row_major> ah[2], al[2];
#pragma unroll
            for (int i = 0; i < 2; i++) {
                wmma::load_matrix_sync(ah[i], sAh + (size_t)(wm + 16 * i) * LDS_AB + k0, LDS_AB);
                wmma::load_matrix_sync(al[i], sAl + (size_t)(wm + 16 * i) * LDS_AB + k0, LDS_AB);
            }
#pragma unroll
            for (int j = 0; j < 4; j++) {
                wmma::fragment<wmma::matrix_b, 16, 16, 16, __nv_bfloat16, wmma::col_major> bh, bl;
                wmma::load_matrix_sync(bh, sBh + (size_t)(wn + 16 * j) * LDS_AB + k0, LDS_AB);
                wmma::load_matrix_sync(bl, sBl + (size_t)(wn + 16 * j) * LDS_AB + k0, LDS_AB);
#pragma unroll
                for (int i = 0; i < 2; i++) {
                    wmma::mma_sync(acc[i][j], ah[i], bh, acc[i][j]);
                    wmma::mma_sync(acc[i][j], ah[i], bl, acc[i][j]);
                    wmma::mma_sync(acc[i][j], al[i], bh, acc[i][j]);
                }
            }
        }
    }

    // epilogue
    __syncthreads();
    float* sC = (float*)smem;
#pragma unroll
    for (int i = 0; i < 2; i++)
#pragma unroll
        for (int j = 0; j < 4; j++)
            wmma::store_matrix_sync(sC + (size_t)(wm + 16 * i) * LDS_C + wn + 16 * j,
                                    acc[i][j], LDS_C, wmma::mem_row_major);
    __syncthreads();

    float st_s[4] = {0.f, 0.f, 0.f, 0.f};
    float st_q[4] = {0.f, 0.f, 0.f, 0.f};
#pragma unroll
    for (int it = 0; it < 16; it++) {
        const int idx = tid + it * 256;
        const int row = idx >> 5;
        const int c = (idx & 31) << 2;
        const int m = bm + row;
        if (m < M) {
            const int n = bn + c;
            float4 o = *(const float4*)(sC + (size_t)row * LDS_C + c);
            if (BIAS) {
                float4 b4 = *(const float4*)&bias[n];
                o.x += b4.x; o.y += b4.y; o.z += b4.z; o.w += b4.w;
            }
            if (RELU) {
                o.x = fmaxf(o.x, 0.f); o.y = fmaxf(o.y, 0.f);
                o.z = fmaxf(o.z, 0.f); o.w = fmaxf(o.w, 0.f);
            }
            if (RES) {
                float4 r4 = *(const float4*)&res[(size_t)m * Co + n];
                if (RESBN) {
                    float4 s4 = *(const float4*)(coefR + c);
                    float4 t4 = *(const float4*)(coefR + 128 + c);
                    r4.x = r4.x * s4.x + t4.x; r4.y = r4.y * s4.y + t4.y;
                    r4.z = r4.z * s4.z + t4.z; r4.w = r4.w * s4.w + t4.w;
                }
                o.x += r4.x; o.y += r4.y; o.z += r4.z; o.w += r4.w;
            }
            *(float4*)&Y[(size_t)m * Co + n] = o;
            if (STATS) {
                st_s[0] += o.x; st_s[1] += o.y; st_s[2] += o.z; st_s[3] += o.w;
                st_q[0] += o.x * o.x; st_q[1] += o.y * o.y;
                st_q[2] += o.z * o.z; st_q[3] += o.w * o.w;
            }
        }
    }
    if (STATS) {
        __syncthreads();
        float* sP = (float*)smem;
#pragma unroll
        for (int j = 0; j < 4; j++) { sP[tid * 8 + j] = st_s[j]; sP[tid * 8 + 4 + j] = st_q[j]; }
        __syncthreads();
        if (tid < 128) {
            const int cg = tid >> 2, sub = tid & 3;
            float s = 0.f, qq = 0.f;
#pragma unroll
            for (int rg = 0; rg < 8; rg++) {
                const int tt = rg * 32 + cg;
                s += sP[tt * 8 + sub];
                qq += sP[tt * 8 + 4 + sub];
            }
            atomicAdd(&stats[bn + tid], s);
            atomicAdd(&stats[128 + bn + tid], qq);
        }
    }
}

template <bool RELU, bool BIAS, bool RES, bool BNIN, bool RESBN, bool STATS>
__global__ void __launch_bounds__(256, 2)
tc_gemm_kernel(const float* __restrict__ X,
               const __nv_bfloat16* __restrict__ WH, const __nv_bfloat16* __restrict__ WL,
               const float* __restrict__ bias, const float* __restrict__ res,
               const float* __restrict__ coefA, const float* __restrict__ coefR,
               float* __restrict__ stats, float* __restrict__ Y, int M, int K, int Co) {
    extern __shared__ char smem[];
    gemm_core<RELU, BIAS, RES, BNIN, RESBN, STATS>(
        X, WH, WL, bias, res, coefA, coefR, stats, Y, M, K, Co,
        blockIdx.x * 128, blockIdx.y * 128, smem);
}

// batched q/k/v projections: z selects input/weight/output
__global__ void __launch_bounds__(256, 2)
qkv_gemm_kernel(const float* __restrict__ q, const float* __restrict__ k,
                const float* __restrict__ v) {
    extern __shared__ char smem[];
    const int z = blockIdx.z;
    const float* X = (z == 0) ? q : (z == 1) ? k : v;
    float* Y = (z == 0) ? g_qd : (z == 1) ? g_kd : g_vd;
    gemm_core<false, false, false, false, false, false>(
        X, g_wh + z * 16384, g_wl + z * 16384,
        nullptr, nullptr, nullptr, nullptr, nullptr, Y, NN, CD, CD,
        blockIdx.x * 128, 0, smem);
}

// ---------------- edge bias + dst histogram (fused) ----------------
__global__ void __launch_bounds__(256)
eb_kernel(const float* __restrict__ ef, const float* __restrict__ We,
          const float* __restrict__ be, const int* __restrict__ dst) {
    __shared__ float sWe[HH * EDD];
    __shared__ float sbe[HH];
    for (int i = threadIdx.x; i < HH * EDD; i += 256) sWe[i] = We[i];
    if (threadIdx.x < HH) sbe[threadIdx.x] = be[threadIdx.x];
    __syncthreads();

    const int e = blockIdx.x * 256 + threadIdx.x;
    atomicAdd(&g_cnt[dst[e]], 1);
    const float4* efp = (const float4*)(ef + (size_t)e * EDD);
    float acc[HH];
#pragma unroll
    for (int h = 0; h < HH; h++) acc[h] = sbe[h];
#pragma unroll
    for (int j4 = 0; j4 < EDD / 4; j4++) {
        float4 v = efp[j4];
#pragma unroll
        for (int h = 0; h < HH; h++) {
            float4 w = *(const float4*)&sWe[h * EDD + j4 * 4];
            acc[h] += v.x * w.x + v.y * w.y + v.z * w.z + v.w * w.w;
        }
    }
    float4 o0 = make_float4(acc[0], acc[1], acc[2], acc[3]);
    float4 o1 = make_float4(acc[4], acc[5], acc[6], acc[7]);
    ((float4*)g_eb)[(size_t)e * 2 + 0] = o0;
    ((float4*)g_eb)[(size_t)e * 2 + 1] = o1;
}

// ---------------- BN coefficients from stats ----------------
__global__ void bn_coef_kernel(const float* __restrict__ sums,
                               const float* __restrict__ g, const float* __restrict__ b,
                               float* __restrict__ coef) {
    const int c = threadIdx.x;
    const float inv = 1.f / (float)NN;
    const float mu = sums[c] * inv;
    const float var = sums[128 + c] * inv - mu * mu;
    const float rs = rsqrtf(var + EPS);
    const float sc = rs * g[c];
    coef[c] = sc;
    coef[128 + c] = b[c] - mu * sc;
}

// ---------------- final apply ----------------
__global__ void __launch_bounds__(256)
bn_apply_kernel(const float* __restrict__ X, float* __restrict__ Y,
                const float* __restrict__ coef) {
    const int i = blockIdx.x * 256 + threadIdx.x;
    const int c = i & (CD - 1);
    Y[i] = X[i] * coef[c] + coef[128 + c];
}

// ---------------- launcher ----------------
extern "C" void kernel_launch(void* const* d_in, const int* in_sizes, int n_in,
                              void* d_out, int out_size) {
    const float* q   = (const float*)d_in[0];
    const float* k   = (const float*)d_in[1];
    const float* v   = (const float*)d_in[2];
    const float* ef  = (const float*)d_in[3];
    const int*   src = (const int*)d_in[4];
    const int*   dst = (const int*)d_in[5];
    const float* Wq  = (const float*)d_in[6];
    const float* Wk  = (const float*)d_in[7];
    const float* Wv  = (const float*)d_in[8];
    const float* We  = (const float*)d_in[9];
    const float* be  = (const float*)d_in[10];
    const float* Wo  = (const float*)d_in[11];
    const float* W1  = (const float*)d_in[12];
    const float* b1  = (const float*)d_in[13];
    const float* W2  = (const float*)d_in[14];
    const float* b2  = (const float*)d_in[15];
    const float* g1  = (const float*)d_in[16];
    const float* bt1 = (const float*)d_in[17];
    const float* g2  = (const float*)d_in[18];
    const float* bt2 = (const float*)d_in[19];
    float* out = (float*)d_out;

    float* p_agg; cudaGetSymbolAddress((void**)&p_agg, g_agg);
    float* p_rst; cudaGetSymbolAddress((void**)&p_rst, g_rst);
    float* p_h1; cudaGetSymbolAddress((void**)&p_h1, g_h1);
    float* p_h2; cudaGetSymbolAddress((void**)&p_h2, g_h2);
    float* p_stats; cudaGetSymbolAddress((void**)&p_stats, g_stats);
    float* p_coef; cudaGetSymbolAddress((void**)&p_coef, g_coef);
    __nv_bfloat16* p_wh; cudaGetSymbolAddress((void**)&p_wh, g_wh);
    __nv_bfloat16* p_wl; cudaGetSymbolAddress((void**)&p_wl, g_wl);

    cudaFuncSetAttribute(qkv_gemm_kernel, cudaFuncAttributeMaxDynamicSharedMemorySize, SMEM_TC);
    cudaFuncSetAttribute(tc_gemm_kernel<false, false, true,  false, false, true >, cudaFuncAttributeMaxDynamicSharedMemorySize, SMEM_TC);
    cudaFuncSetAttribute(tc_gemm_kernel<true,  true,  false, true,  false, false>, cudaFuncAttributeMaxDynamicSharedMemorySize, SMEM_TC);
    cudaFuncSetAttribute(tc_gemm_kernel<false, true,  true,  false, true,  true >, cudaFuncAttributeMaxDynamicSharedMemorySize, SMEM_TC);

    initconv_kernel<<<WTOT / 256, 256>>>(Wq, Wk, Wv, Wo, W1, W2);

    const dim3 gQKV(313, 1, 3);
    const dim3 gC(313, 1);
    const dim3 gH(313, 2);

    // projections (batched, one launch)
    qkv_gemm_kernel<<<gQKV, 256, SMEM_TC>>>(q, k, v);

    // edge phase
    eb_kernel<<<EE / 256, 256>>>(ef, We, be, dst);
    scan_kernel<<<1, 1024>>>();
    scatter_kernel<<<EE / 256, 256>>>(src, dst);
    attn_kernel<<<NN / 8, 256>>>();

    // out proj + residual, stats for BN1 fused
    tc_gemm_kernel<false, false, true, false, false, true><<<gC, 256, SMEM_TC>>>(
        p_agg, p_wh + WOFF_O, p_wl + WOFF_O, nullptr, q, nullptr, nullptr, p_stats, p_rst, NN, CD, CD);
    bn_coef_kernel<<<1, 128>>>(p_stats, g1, bt1, p_coef);

    // FFN
    tc_gemm_kernel<true, true, false, true, false, false><<<gH, 256, SMEM_TC>>>(
        p_rst, p_wh + WOFF_1, p_wl + WOFF_1, b1, nullptr, p_coef, nullptr, nullptr, p_h1, NN, CD, C2);
    tc_gemm_kernel<false, true, true, false, true, true><<<gC, 256, SMEM_TC>>>(
        p_h1, p_wh + WOFF_2, p_wl + WOFF_2, b2, p_rst, nullptr, p_coef, p_stats + 2 * CD, p_h2, NN, C2, CD);
    bn_coef_kernel<<<1, 128>>>(p_stats + 2 * CD, g2, bt2, p_coef + 2 * CD);
    bn_apply_kernel<<<NN * CD / 256, 256>>>(p_h2, out, p_coef + 2 * CD);
}

// round 10
// speedup vs baseline: 2.1893x; 1.1574x over previous
#include <cuda_runtime.h>
#include <cuda_bf16.h>
#include <mma.h>
#include <cstdint>

using namespace nvcuda;

// ---------------- problem constants ----------------
#define NN 40000      // nodes
#define EE 640000     // edges
#define CD 128        // channels (= IN = H*D)
#define HH 8          // heads
#define DD 16         // dim per head
#define EDD 64        // edge feature dim
#define C2 256        // FFN hidden
#define EPS 1e-5f
#define NB 157        // ceil(NN/256)

// ---------------- scratch (static device globals; no allocs allowed) ----------------
__device__ float    g_qd[(size_t)NN * CD];
__device__ float    g_kd[(size_t)NN * CD];
__device__ float    g_vd[(size_t)NN * CD];
__device__ float    g_eb[(size_t)EE * HH];    // per-edge bias (edge order)
__device__ float    g_ebp[(size_t)EE * HH];   // per-edge bias (CSR order)
__device__ float    g_agg[(size_t)NN * CD];
__device__ float    g_rst[(size_t)NN * CD];
__device__ float    g_h1[(size_t)NN * C2];
__device__ float    g_h2[(size_t)NN * CD];
__device__ float    g_stats[4 * CD];
__device__ float    g_coef[4 * CD];
// CSR
__device__ int      g_cnt[NN];
__device__ int      g_pos[NN];
__device__ int      g_row[NN + 1];
__device__ int      g_bsum[NB];
__device__ int      g_esrc[EE];
// preconverted weights (bf16 hi/lo)
#define WOFF_Q  0
#define WOFF_K  16384
#define WOFF_V  32768
#define WOFF_O  49152
#define WOFF_1  65536
#define WOFF_2  98304
#define WTOT    131072
__device__ __align__(16) __nv_bfloat16 g_wh[WTOT];
__device__ __align__(16) __nv_bfloat16 g_wl[WTOT];

// ---------------- cp.async helpers ----------------
__device__ __forceinline__ void cp_async16(uint32_t saddr, const void* gaddr) {
    asm volatile("cp.async.ca.shared.global [%0], [%1], 16;" :: "r"(saddr), "l"(gaddr));
}
#define CP_COMMIT() asm volatile("cp.async.commit_group;" ::: "memory")
#define CP_WAIT0()  asm volatile("cp.async.wait_group 0;" ::: "memory")

// ---------------- init + weight preconversion (single launch) ----------------
__global__ void initconv_kernel(const float* __restrict__ Wq, const float* __restrict__ Wk,
                                const float* __restrict__ Wv, const float* __restrict__ Wo,
                                const float* __restrict__ W1, const float* __restrict__ W2) {
    int i = blockIdx.x * 256 + threadIdx.x;
    if (i < NN) { g_cnt[i] = 0; g_pos[i] = 0; }
    if (i < 4 * CD) g_stats[i] = 0.f;
    if (i < WTOT) {
        const float* src; int off;
        if (i < WOFF_K)      { src = Wq; off = i - WOFF_Q; }
        else if (i < WOFF_V) { src = Wk; off = i - WOFF_K; }
        else if (i < WOFF_O) { src = Wv; off = i - WOFF_V; }
        else if (i < WOFF_1) { src = Wo; off = i - WOFF_O; }
        else if (i < WOFF_2) { src = W1; off = i - WOFF_1; }
        else                 { src = W2; off = i - WOFF_2; }
        float v = src[off];
        __nv_bfloat16 h = __float2bfloat16(v);
        g_wh[i] = h;
        g_wl[i] = __float2bfloat16(v - __bfloat162float(h));
    }
}

// ---------------- multi-block exclusive scan (3 phases) ----------------
__device__ __forceinline__ int block_scan256(int x, int* total) {
    // returns inclusive scan of x across 256 threads; *total = block sum
    __shared__ int ws[8];
    const int t = threadIdx.x, lane = t & 31, wid = t >> 5;
    int v = x;
#pragma unroll
    for (int o = 1; o < 32; o <<= 1) {
        int u = __shfl_up_sync(0xffffffffu, v, o);
        if (lane >= o) v += u;
    }
    if (lane == 31) ws[wid] = v;
    __syncthreads();
    if (wid == 0 && lane < 8) {
        int w = ws[lane];
#pragma unroll
        for (int o = 1; o < 8; o <<= 1) {
            int u = __shfl_up_sync(0x000000ffu, w, o);
            if (lane >= o) w += u;
        }
        ws[lane] = w;
    }
    __syncthreads();
    const int off = (wid > 0) ? ws[wid - 1] : 0;
    *total = ws[7];
    return off + v;
}

__global__ void __launch_bounds__(256)
scan1_kernel() {
    const int idx = blockIdx.x * 256 + threadIdx.x;
    int x = (idx < NN) ? g_cnt[idx] : 0;
    int total;
    int inc = block_scan256(x, &total);
    if (idx < NN) g_row[idx] = inc - x;          // block-local exclusive
    if (threadIdx.x == 255) g_bsum[blockIdx.x] = total;
}

__global__ void __launch_bounds__(256)
scan2_kernel() {
    const int t = threadIdx.x;
    int x = (t < NB) ? g_bsum[t] : 0;
    int total;
    int inc = block_scan256(x, &total);
    if (t < NB) g_bsum[t] = inc - x;             // exclusive block offsets
}

__global__ void __launch_bounds__(256)
scan3_kernel() {
    const int idx = blockIdx.x * 256 + threadIdx.x;
    if (idx < NN) g_row[idx] += g_bsum[blockIdx.x];
    if (idx == 0) g_row[NN] = EE;
}

// ---------------- scatter: build CSR adjacency + permute eb into CSR order ----------------
__global__ void scatter_kernel(const int* __restrict__ src, const int* __restrict__ dst) {
    int e = blockIdx.x * 256 + threadIdx.x;
    const int d = dst[e];
    int p = atomicAdd(&g_pos[d], 1);
    int o = g_row[d] + p;
    g_esrc[o] = src[e];
    float4 a = ((const float4*)g_eb)[(size_t)e * 2 + 0];
    float4 b = ((const float4*)g_eb)[(size_t)e * 2 + 1];
    ((float4*)g_ebp)[(size_t)o * 2 + 0] = a;
    ((float4*)g_ebp)[(size_t)o * 2 + 1] = b;
}

// ---------------- fused one-pass attention (warp per node, pipelined) ----------------
__global__ void __launch_bounds__(256)
attn_kernel() {
    const int warpId = (blockIdx.x * 256 + threadIdx.x) >> 5;
    const int lane = threadIdx.x & 31;
    if (warpId >= NN) return;
    const int n = warpId;
    const int r0 = g_row[n], r1 = g_row[n + 1];
    const int h = lane >> 2;

    float4 qv = ((const float4*)g_qd)[(size_t)n * 32 + lane];

    float m = -3.0e38f, den = 0.f;
    float4 acc = make_float4(0.f, 0.f, 0.f, 0.f);
    if (r0 < r1) {
        int s = g_esrc[r0];
        float4 kv = ((const float4*)g_kd)[(size_t)s * 32 + lane];
        float4 vv = ((const float4*)g_vd)[(size_t)s * 32 + lane];
        float ebv = __ldg(&g_ebp[(size_t)r0 * HH + h]);
        for (int i = r0; i < r1; i++) {
            float4 nkv = kv, nvv = vv;
            float nebv = 0.f;
            if (i + 1 < r1) {
                const int ns = g_esrc[i + 1];
                nkv = ((const float4*)g_kd)[(size_t)ns * 32 + lane];
                nvv = ((const float4*)g_vd)[(size_t)ns * 32 + lane];
                nebv = __ldg(&g_ebp[(size_t)(i + 1) * HH + h]);
            }
            float p = qv.x * kv.x + qv.y * kv.y + qv.z * kv.z + qv.w * kv.w;
            p += __shfl_xor_sync(0xffffffffu, p, 1);
            p += __shfl_xor_sync(0xffffffffu, p, 2);
            const float sc = p * 0.25f + ebv;
            const float nm = fmaxf(m, sc);
            const float corr = __expf(m - nm);
            const float w = __expf(sc - nm);
            m = nm;
            den = den * corr + w;
            acc.x = acc.x * corr + w * vv.x;
            acc.y = acc.y * corr + w * vv.y;
            acc.z = acc.z * corr + w * vv.z;
            acc.w = acc.w * corr + w * vv.w;
            kv = nkv; vv = nvv; ebv = nebv;
        }
    }
    const float inv = (den > 0.f) ? (1.f / den) : 0.f;
    acc.x *= inv; acc.y *= inv; acc.z *= inv; acc.w *= inv;
    ((float4*)g_agg)[(size_t)n * 32 + lane] = acc;
}

// ---------------- WMMA bf16-split GEMM core ----------------
#define LDS_AB 72
#define OFF_AH 0
#define OFF_AL (OFF_AH + 128 * LDS_AB * 2)
#define OFF_BH (OFF_AL + 128 * LDS_AB * 2)
#define OFF_BL (OFF_BH + 128 * LDS_AB * 2)
#define SMEM_TC (OFF_BL + 128 * LDS_AB * 2)  // 73728 bytes
#define LDS_C 132

__device__ __forceinline__ void cvt_storeA(char* smem, int row, int c4, float4 v) {
    __nv_bfloat162 h0 = __floats2bfloat162_rn(v.x, v.y);
    __nv_bfloat162 h1 = __floats2bfloat162_rn(v.z, v.w);
    float2 f0 = __bfloat1622float2(h0);
    float2 f1 = __bfloat1622float2(h1);
    __nv_bfloat162 l0 = __floats2bfloat162_rn(v.x - f0.x, v.y - f0.y);
    __nv_bfloat162 l1 = __floats2bfloat162_rn(v.z - f1.x, v.w - f1.y);
    uint2 ph, pl;
    ph.x = *(uint32_t*)&h0; ph.y = *(uint32_t*)&h1;
    pl.x = *(uint32_t*)&l0; pl.y = *(uint32_t*)&l1;
    *(uint2*)(smem + OFF_AH + ((size_t)row * LDS_AB + c4) * 2) = ph;
    *(uint2*)(smem + OFF_AL + ((size_t)row * LDS_AB + c4) * 2) = pl;
}

template <bool RELU, bool BIAS, bool RES, bool BNIN, bool RESBN, bool STATS>
__device__ __forceinline__ void gemm_core(
    const float* __restrict__ X,
    const __nv_bfloat16* __restrict__ WH, const __nv_bfloat16* __restrict__ WL,
    const float* __restrict__ bias, const float* __restrict__ res,
    const float* __restrict__ coefA, const float* __restrict__ coefR,
    float* __restrict__ stats, float* __restrict__ Y,
    int M, int K, int Co, int bm, int bn, char* smem) {
    const int tid = threadIdx.x;
    const int warp = tid >> 5;
    const int wm = (warp & 3) * 32;
    const int wn = (warp >> 2) * 64;
    const uint32_t sb = (uint32_t)__cvta_generic_to_shared(smem);

    wmma::fragment<wmma::accumulator, 16, 16, 16, float> acc[2][4];
#pragma unroll
    for (int i = 0; i < 2; i++)
#pragma unroll
        for (int j = 0; j < 4; j++)
            wmma::fill_fragment(acc[i][j], 0.f);

    const __nv_bfloat16* sAh = (const __nv_bfloat16*)(smem + OFF_AH);
    const __nv_bfloat16* sAl = (const __nv_bfloat16*)(smem + OFF_AL);
    const __nv_bfloat16* sBh = (const __nv_bfloat16*)(smem + OFF_BH);
    const __nv_bfloat16* sBl = (const __nv_bfloat16*)(smem + OFF_BL);

    const int nch = K >> 6;
    for (int ch = 0; ch < nch; ch++) {
        const int kc0 = ch << 6;
        __syncthreads();
        // B: async copy of preconverted bf16 hi/lo (overlaps with A conversion)
#pragma unroll
        for (int it = 0; it < 4; it++) {
            const int idx = tid + it * 256;
            const int row = idx >> 3;
            const int c8 = (idx & 7) << 3;
            const size_t g = (size_t)(bn + row) * K + kc0 + c8;
            const uint32_t so = sb + OFF_BH + (uint32_t)(row * LDS_AB + c8) * 2;
            cp_async16(so, WH + g);
            cp_async16(so + (OFF_BL - OFF_BH), WL + g);
        }
        CP_COMMIT();
        // A: convert 128x64 fp32 -> bf16 hi/lo (optionally BN-normalized)
#pragma unroll
        for (int it = 0; it < 8; it++) {
            const int idx = tid + it * 256;
            const int row = idx >> 4;
            const int c4 = (idx & 15) << 2;
            const int r = min(bm + row, M - 1);
            float4 v = *(const float4*)(X + (size_t)r * K + kc0 + c4);
            if (BNIN) {
                const int c = kc0 + c4;
                float4 s4 = *(const float4*)(coefA + c);
                float4 t4 = *(const float4*)(coefA + 128 + c);
                v.x = v.x * s4.x + t4.x; v.y = v.y * s4.y + t4.y;
                v.z = v.z * s4.z + t4.z; v.w = v.w * s4.w + t4.w;
            }
            cvt_storeA(smem, row, c4, v);
        }
        CP_WAIT0();
        __syncthreads();

#pragma unroll
        for (int ks = 0; ks < 4; ks++) {
            const int k0 = ks * 16;
            wmma::fragment<wmma::matrix_a, 16, 16, 16, __nv_bfloat16, wmma::row_major> ah[2], al[2];
#pragma unroll
            for (int i = 0; i < 2; i++) {
                wmma::load_matrix_sync(ah[i], sAh + (size_t)(wm + 16 * i) * LDS_AB + k0, LDS_AB);
                wmma::load_matrix_sync(al[i], sAl + (size_t)(wm + 16 * i) * LDS_AB + k0, LDS_AB);
            }
#pragma unroll
            for (int j = 0; j < 4; j++) {
                wmma::fragment<wmma::matrix_b, 16, 16, 16, __nv_bfloat16, wmma::col_major> bh, bl;
                wmma::load_matrix_sync(bh, sBh + (size_t)(wn + 16 * j) * LDS_AB + k0, LDS_AB);
                wmma::load_matrix_sync(bl, sBl + (size_t)(wn + 16 * j) * LDS_AB + k0, LDS_AB);
#pragma unroll
                for (int i = 0; i < 2; i++) {
                    wmma::mma_sync(acc[i][j], ah[i], bh, acc[i][j]);
                    wmma::mma_sync(acc[i][j], ah[i], bl, acc[i][j]);
                    wmma::mma_sync(acc[i][j], al[i], bh, acc[i][j]);
                }
            }
        }
    }

    // epilogue
    __syncthreads();
    float* sC = (float*)smem;
#pragma unroll
    for (int i = 0; i < 2; i++)
#pragma unroll
        for (int j = 0; j < 4; j++)
            wmma::store_matrix_sync(sC + (size_t)(wm + 16 * i) * LDS_C + wn + 16 * j,
                                    acc[i][j], LDS_C, wmma::mem_row_major);
    __syncthreads();

    float st_s[4] = {0.f, 0.f, 0.f, 0.f};
    float st_q[4] = {0.f, 0.f, 0.f, 0.f};
#pragma unroll
    for (int it = 0; it < 16; it++) {
        const int idx = tid + it * 256;
        const int row = idx >> 5;
        const int c = (idx & 31) << 2;
        const int m = bm + row;
        if (m < M) {
            const int n = bn + c;
            float4 o = *(const float4*)(sC + (size_t)row * LDS_C + c);
            if (BIAS) {
                float4 b4 = *(const float4*)&bias[n];
                o.x += b4.x; o.y += b4.y; o.z += b4.z; o.w += b4.w;
            }
            if (RELU) {
                o.x = fmaxf(o.x, 0.f); o.y = fmaxf(o.y, 0.f);
                o.z = fmaxf(o.z, 0.f); o.w = fmaxf(o.w, 0.f);
            }
            if (RES) {
                float4 r4 = *(const float4*)&res[(size_t)m * Co + n];
                if (RESBN) {
                    float4 s4 = *(const float4*)(coefR + c);
                    float4 t4 = *(const float4*)(coefR + 128 + c);
                    r4.x = r4.x * s4.x + t4.x; r4.y = r4.y * s4.y + t4.y;
                    r4.z = r4.z * s4.z + t4.z; r4.w = r4.w * s4.w + t4.w;
                }
                o.x += r4.x; o.y += r4.y; o.z += r4.z; o.w += r4.w;
            }
            *(float4*)&Y[(size_t)m * Co + n] = o;
            if (STATS) {
                st_s[0] += o.x; st_s[1] += o.y; st_s[2] += o.z; st_s[3] += o.w;
                st_q[0] += o.x * o.x; st_q[1] += o.y * o.y;
                st_q[2] += o.z * o.z; st_q[3] += o.w * o.w;
            }
        }
    }
    if (STATS) {
        __syncthreads();
        float* sP = (float*)smem;
#pragma unroll
        for (int j = 0; j < 4; j++) { sP[tid * 8 + j] = st_s[j]; sP[tid * 8 + 4 + j] = st_q[j]; }
        __syncthreads();
        if (tid < 128) {
            const int cg = tid >> 2, sub = tid & 3;
            float s = 0.f, qq = 0.f;
#pragma unroll
            for (int rg = 0; rg < 8; rg++) {
                const int tt = rg * 32 + cg;
                s += sP[tt * 8 + sub];
                qq += sP[tt * 8 + 4 + sub];
            }
            atomicAdd(&stats[bn + tid], s);
            atomicAdd(&stats[128 + bn + tid], qq);
        }
    }
}

template <bool RELU, bool BIAS, bool RES, bool BNIN, bool RESBN, bool STATS>
__global__ void __launch_bounds__(256, 2)
tc_gemm_kernel(const float* __restrict__ X,
               const __nv_bfloat16* __restrict__ WH, const __nv_bfloat16* __restrict__ WL,
               const float* __restrict__ bias, const float* __restrict__ res,
               const float* __restrict__ coefA, const float* __restrict__ coefR,
               float* __restrict__ stats, float* __restrict__ Y, int M, int K, int Co) {
    extern __shared__ char smem[];
    gemm_core<RELU, BIAS, RES, BNIN, RESBN, STATS>(
        X, WH, WL, bias, res, coefA, coefR, stats, Y, M, K, Co,
        blockIdx.x * 128, blockIdx.y * 128, smem);
}

__global__ void __launch_bounds__(256, 2)
qkv_gemm_kernel(const float* __restrict__ q, const float* __restrict__ k,
                const float* __restrict__ v) {
    extern __shared__ char smem[];
    const int z = blockIdx.z;
    const float* X = (z == 0) ? q : (z == 1) ? k : v;
    float* Y = (z == 0) ? g_qd : (z == 1) ? g_kd : g_vd;
    gemm_core<false, false, false, false, false, false>(
        X, g_wh + z * 16384, g_wl + z * 16384,
        nullptr, nullptr, nullptr, nullptr, nullptr, Y, NN, CD, CD,
        blockIdx.x * 128, 0, smem);
}

// ---------------- edge bias + dst histogram (fused) ----------------
__global__ void __launch_bounds__(256)
eb_kernel(const float* __restrict__ ef, const float* __restrict__ We,
          const float* __restrict__ be, const int* __restrict__ dst) {
    __shared__ float sWe[HH * EDD];
    __shared__ float sbe[HH];
    for (int i = threadIdx.x; i < HH * EDD; i += 256) sWe[i] = We[i];
    if (threadIdx.x < HH) sbe[threadIdx.x] = be[threadIdx.x];
    __syncthreads();

    const int e = blockIdx.x * 256 + threadIdx.x;
    atomicAdd(&g_cnt[dst[e]], 1);
    const float4* efp = (const float4*)(ef + (size_t)e * EDD);
    float acc[HH];
#pragma unroll
    for (int h = 0; h < HH; h++) acc[h] = sbe[h];
#pragma unroll
    for (int j4 = 0; j4 < EDD / 4; j4++) {
        float4 v = efp[j4];
#pragma unroll
        for (int h = 0; h < HH; h++) {
            float4 w = *(const float4*)&sWe[h * EDD + j4 * 4];
            acc[h] += v.x * w.x + v.y * w.y + v.z * w.z + v.w * w.w;
        }
    }
    float4 o0 = make_float4(acc[0], acc[1], acc[2], acc[3]);
    float4 o1 = make_float4(acc[4], acc[5], acc[6], acc[7]);
    ((float4*)g_eb)[(size_t)e * 2 + 0] = o0;
    ((float4*)g_eb)[(size_t)e * 2 + 1] = o1;
}

// ---------------- BN coefficients ----------------
__global__ void bn_coef_kernel(const float* __restrict__ sums,
                               const float* __restrict__ g, const float* __restrict__ b,
                               float* __restrict__ coef) {
    const int c = threadIdx.x;
    const float inv = 1.f / (float)NN;
    const float mu = sums[c] * inv;
    const float var = sums[128 + c] * inv - mu * mu;
    const float rs = rsqrtf(var + EPS);
    const float sc = rs * g[c];
    coef[c] = sc;
    coef[128 + c] = b[c] - mu * sc;
}

// ---------------- final apply ----------------
__global__ void __launch_bounds__(256)
bn_apply_kernel(const float* __restrict__ X, float* __restrict__ Y,
                const float* __restrict__ coef) {
    const int i = blockIdx.x * 256 + threadIdx.x;
    const int c = i & (CD - 1);
    Y[i] = X[i] * coef[c] + coef[128 + c];
}

// ---------------- launcher ----------------
extern "C" void kernel_launch(void* const* d_in, const int* in_sizes, int n_in,
                              void* d_out, int out_size) {
    const float* q   = (const float*)d_in[0];
    const float* k   = (const float*)d_in[1];
    const float* v   = (const float*)d_in[2];
    const float* ef  = (const float*)d_in[3];
    const int*   src = (const int*)d_in[4];
    const int*   dst = (const int*)d_in[5];
    const float* Wq  = (const float*)d_in[6];
    const float* Wk  = (const float*)d_in[7];
    const float* Wv  = (const float*)d_in[8];
    const float* We  = (const float*)d_in[9];
    const float* be  = (const float*)d_in[10];
    const float* Wo  = (const float*)d_in[11];
    const float* W1  = (const float*)d_in[12];
    const float* b1  = (const float*)d_in[13];
    const float* W2  = (const float*)d_in[14];
    const float* b2  = (const float*)d_in[15];
    const float* g1  = (const float*)d_in[16];
    const float* bt1 = (const float*)d_in[17];
    const float* g2  = (const float*)d_in[18];
    const float* bt2 = (const float*)d_in[19];
    float* out = (float*)d_out;

    float* p_agg; cudaGetSymbolAddress((void**)&p_agg, g_agg);
    float* p_rst; cudaGetSymbolAddress((void**)&p_rst, g_rst);
    float* p_h1; cudaGetSymbolAddress((void**)&p_h1, g_h1);
    float* p_h2; cudaGetSymbolAddress((void**)&p_h2, g_h2);
    float* p_stats; cudaGetSymbolAddress((void**)&p_stats, g_stats);
    float* p_coef; cudaGetSymbolAddress((void**)&p_coef, g_coef);
    __nv_bfloat16* p_wh; cudaGetSymbolAddress((void**)&p_wh, g_wh);
    __nv_bfloat16* p_wl; cudaGetSymbolAddress((void**)&p_wl, g_wl);

    // lazy-created side stream + events (first call is the uncaptured correctness run)
    static cudaStream_t s2 = nullptr;
    static cudaEvent_t evF = nullptr, evJ = nullptr;
    if (!s2) {
        cudaStreamCreateWithFlags(&s2, cudaStreamNonBlocking);
        cudaEventCreateWithFlags(&evF, cudaEventDisableTiming);
        cudaEventCreateWithFlags(&evJ, cudaEventDisableTiming);
    }

    cudaFuncSetAttribute(qkv_gemm_kernel, cudaFuncAttributeMaxDynamicSharedMemorySize, SMEM_TC);
    cudaFuncSetAttribute(tc_gemm_kernel<false, false, true,  false, false, true >, cudaFuncAttributeMaxDynamicSharedMemorySize, SMEM_TC);
    cudaFuncSetAttribute(tc_gemm_kernel<true,  true,  false, true,  false, false>, cudaFuncAttributeMaxDynamicSharedMemorySize, SMEM_TC);
    cudaFuncSetAttribute(tc_gemm_kernel<false, true,  true,  false, true,  true >, cudaFuncAttributeMaxDynamicSharedMemorySize, SMEM_TC);

    initconv_kernel<<<WTOT / 256, 256>>>(Wq, Wk, Wv, Wo, W1, W2);

    // fork: edge preprocessing on s2 runs concurrently with qkv GEMM on main stream
    cudaEventRecord(evF, 0);
    cudaStreamWaitEvent(s2, evF, 0);

    eb_kernel<<<EE / 256, 256, 0, s2>>>(ef, We, be, dst);
    scan1_kernel<<<NB, 256, 0, s2>>>();
    scan2_kernel<<<1, 256, 0, s2>>>();
    scan3_kernel<<<NB, 256, 0, s2>>>();
    scatter_kernel<<<EE / 256, 256, 0, s2>>>(src, dst);
    cudaEventRecord(evJ, s2);

    const dim3 gQKV(313, 1, 3);
    const dim3 gC(313, 1);
    const dim3 gH(313, 2);

    qkv_gemm_kernel<<<gQKV, 256, SMEM_TC>>>(q, k, v);

    // join: attn needs both qkv outputs and CSR
    cudaStreamWaitEvent(0, evJ, 0);
    attn_kernel<<<NN / 8, 256>>>();

    // out proj + residual, stats for BN1 fused
    tc_gemm_kernel<false, false, true, false, false, true><<<gC, 256, SMEM_TC>>>(
        p_agg, p_wh + WOFF_O, p_wl + WOFF_O, nullptr, q, nullptr, nullptr, p_stats, p_rst, NN, CD, CD);
    bn_coef_kernel<<<1, 128>>>(p_stats, g1, bt1, p_coef);

    // FFN
    tc_gemm_kernel<true, true, false, true, false, false><<<gH, 256, SMEM_TC>>>(
        p_rst, p_wh + WOFF_1, p_wl + WOFF_1, b1, nullptr, p_coef, nullptr, nullptr, p_h1, NN, CD, C2);
    tc_gemm_kernel<false, true, true, false, true, true><<<gC, 256, SMEM_TC>>>(
        p_h1, p_wh + WOFF_2, p_wl + WOFF_2, b2, p_rst, nullptr, p_coef, p_stats + 2 * CD, p_h2, NN, C2, CD);
    bn_coef_kernel<<<1, 128>>>(p_stats + 2 * CD, g2, bt2, p_coef + 2 * CD);
    bn_apply_kernel<<<NN * CD / 256, 256>>>(p_h2, out, p_coef + 2 * CD);
}

// round 11
// speedup vs baseline: 2.2211x; 1.0145x over previous
#include <cuda_runtime.h>
#include <cuda_bf16.h>
#include <mma.h>
#include <cstdint>

using namespace nvcuda;

// ---------------- problem constants ----------------
#define NN 40000      // nodes
#define EE 640000     // edges
#define CD 128        // channels (= IN = H*D)
#define HH 8          // heads
#define DD 16         // dim per head
#define EDD 64        // edge feature dim
#define C2 256        // FFN hidden
#define EPS 1e-5f
#define NB 157        // ceil(NN/256)

// ---------------- scratch (static device globals; no allocs allowed) ----------------
__device__ float    g_qd[(size_t)NN * CD];
__device__ float    g_kd[(size_t)NN * CD];
__device__ float    g_vd[(size_t)NN * CD];
__device__ float    g_eb[(size_t)EE * HH];    // per-edge bias (edge order)
__device__ float    g_ebp[(size_t)EE * HH];   // per-edge bias (CSR order)
__device__ float    g_agg[(size_t)NN * CD];
__device__ float    g_rst[(size_t)NN * CD];
__device__ float    g_h1[(size_t)NN * C2];
__device__ float    g_h2[(size_t)NN * CD];
__device__ float    g_stats[4 * CD];
__device__ float    g_coef[4 * CD];
// CSR
__device__ int      g_cnt[NN];
__device__ int      g_pos[NN];
__device__ int      g_row[NN + 1];
__device__ int      g_bsum[NB];
__device__ int      g_esrc[EE];
// preconverted weights (bf16 hi/lo)
#define WOFF_Q  0
#define WOFF_K  16384
#define WOFF_V  32768
#define WOFF_O  49152
#define WOFF_1  65536
#define WOFF_2  98304
#define WTOT    131072
__device__ __align__(16) __nv_bfloat16 g_wh[WTOT];
__device__ __align__(16) __nv_bfloat16 g_wl[WTOT];

// ---------------- cp.async helpers ----------------
__device__ __forceinline__ void cp_async16(uint32_t saddr, const void* gaddr) {
    asm volatile("cp.async.ca.shared.global [%0], [%1], 16;" :: "r"(saddr), "l"(gaddr));
}
#define CP_COMMIT() asm volatile("cp.async.commit_group;" ::: "memory")
#define CP_WAIT0()  asm volatile("cp.async.wait_group 0;" ::: "memory")

// ---------------- side-stream init: zero CSR counters ----------------
__global__ void zerocnt_kernel() {
    int i = blockIdx.x * 256 + threadIdx.x;
    if (i < NN) { g_cnt[i] = 0; g_pos[i] = 0; }
}

// ---------------- main-stream init: weights + stats ----------------
__global__ void initconv_kernel(const float* __restrict__ Wq, const float* __restrict__ Wk,
                                const float* __restrict__ Wv, const float* __restrict__ Wo,
                                const float* __restrict__ W1, const float* __restrict__ W2) {
    int i = blockIdx.x * 256 + threadIdx.x;
    if (i < 4 * CD) g_stats[i] = 0.f;
    if (i < WTOT) {
        const float* src; int off;
        if (i < WOFF_K)      { src = Wq; off = i - WOFF_Q; }
        else if (i < WOFF_V) { src = Wk; off = i - WOFF_K; }
        else if (i < WOFF_O) { src = Wv; off = i - WOFF_V; }
        else if (i < WOFF_1) { src = Wo; off = i - WOFF_O; }
        else if (i < WOFF_2) { src = W1; off = i - WOFF_1; }
        else                 { src = W2; off = i - WOFF_2; }
        float v = src[off];
        __nv_bfloat16 h = __float2bfloat16(v);
        g_wh[i] = h;
        g_wl[i] = __float2bfloat16(v - __bfloat162float(h));
    }
}

// ---------------- multi-block exclusive scan (3 phases) ----------------
__device__ __forceinline__ int block_scan256(int x, int* total) {
    __shared__ int ws[8];
    const int t = threadIdx.x, lane = t & 31, wid = t >> 5;
    int v = x;
#pragma unroll
    for (int o = 1; o < 32; o <<= 1) {
        int u = __shfl_up_sync(0xffffffffu, v, o);
        if (lane >= o) v += u;
    }
    if (lane == 31) ws[wid] = v;
    __syncthreads();
    if (wid == 0 && lane < 8) {
        int w = ws[lane];
#pragma unroll
        for (int o = 1; o < 8; o <<= 1) {
            int u = __shfl_up_sync(0x000000ffu, w, o);
            if (lane >= o) w += u;
        }
        ws[lane] = w;
    }
    __syncthreads();
    const int off = (wid > 0) ? ws[wid - 1] : 0;
    *total = ws[7];
    return off + v;
}

__global__ void __launch_bounds__(256)
scan1_kernel() {
    const int idx = blockIdx.x * 256 + threadIdx.x;
    int x = (idx < NN) ? g_cnt[idx] : 0;
    int total;
    int inc = block_scan256(x, &total);
    if (idx < NN) g_row[idx] = inc - x;
    if (threadIdx.x == 255) g_bsum[blockIdx.x] = total;
}

__global__ void __launch_bounds__(256)
scan2_kernel() {
    const int t = threadIdx.x;
    int x = (t < NB) ? g_bsum[t] : 0;
    int total;
    int inc = block_scan256(x, &total);
    if (t < NB) g_bsum[t] = inc - x;
}

__global__ void __launch_bounds__(256)
scan3_kernel() {
    const int idx = blockIdx.x * 256 + threadIdx.x;
    if (idx < NN) g_row[idx] += g_bsum[blockIdx.x];
    if (idx == 0) g_row[NN] = EE;
}

// ---------------- scatter: CSR adjacency + permute eb into CSR order ----------------
__global__ void scatter_kernel(const int* __restrict__ src, const int* __restrict__ dst) {
    int e = blockIdx.x * 256 + threadIdx.x;
    const int d = dst[e];
    int p = atomicAdd(&g_pos[d], 1);
    int o = g_row[d] + p;
    g_esrc[o] = src[e];
    float4 a = ((const float4*)g_eb)[(size_t)e * 2 + 0];
    float4 b = ((const float4*)g_eb)[(size_t)e * 2 + 1];
    ((float4*)g_ebp)[(size_t)o * 2 + 0] = a;
    ((float4*)g_ebp)[(size_t)o * 2 + 1] = b;
}

// ---------------- fused one-pass attention (warp per node, depth-2 pipeline) ----------------
__global__ void __launch_bounds__(256)
attn_kernel() {
    const int warpId = (blockIdx.x * 256 + threadIdx.x) >> 5;
    const int lane = threadIdx.x & 31;
    if (warpId >= NN) return;
    const int n = warpId;
    const int r0 = g_row[n], r1 = g_row[n + 1];
    const int h = lane >> 2;

    float4 qv = ((const float4*)g_qd)[(size_t)n * 32 + lane];

    float m = -3.0e38f, den = 0.f;
    float4 acc = make_float4(0.f, 0.f, 0.f, 0.f);

    float4 kvb0, vvb0, kvb1, vvb1;
    float eb0 = 0.f, eb1 = 0.f;
    if (r0 < r1) {
        const int s = g_esrc[r0];
        kvb0 = ((const float4*)g_kd)[(size_t)s * 32 + lane];
        vvb0 = ((const float4*)g_vd)[(size_t)s * 32 + lane];
        eb0 = __ldg(&g_ebp[(size_t)r0 * HH + h]);
    }
    if (r0 + 1 < r1) {
        const int s = g_esrc[r0 + 1];
        kvb1 = ((const float4*)g_kd)[(size_t)s * 32 + lane];
        vvb1 = ((const float4*)g_vd)[(size_t)s * 32 + lane];
        eb1 = __ldg(&g_ebp[(size_t)(r0 + 1) * HH + h]);
    }

#define ATTN_BODY(KV, VV, EBV)                                              \
    {                                                                       \
        float p = qv.x * (KV).x + qv.y * (KV).y + qv.z * (KV).z + qv.w * (KV).w; \
        p += __shfl_xor_sync(0xffffffffu, p, 1);                            \
        p += __shfl_xor_sync(0xffffffffu, p, 2);                            \
        const float sc = p * 0.25f + (EBV);                                 \
        const float nm = fmaxf(m, sc);                                      \
        const float corr = __expf(m - nm);                                  \
        const float w = __expf(sc - nm);                                    \
        m = nm;                                                             \
        den = den * corr + w;                                               \
        acc.x = acc.x * corr + w * (VV).x;                                  \
        acc.y = acc.y * corr + w * (VV).y;                                  \
        acc.z = acc.z * corr + w * (VV).z;                                  \
        acc.w = acc.w * corr + w * (VV).w;                                  \
    }

    int i = r0;
    while (i < r1) {
        {
            float4 kv = kvb0, vv = vvb0; float ebv = eb0;
            if (i + 2 < r1) {
                const int ns = g_esrc[i + 2];
                kvb0 = ((const float4*)g_kd)[(size_t)ns * 32 + lane];
                vvb0 = ((const float4*)g_vd)[(size_t)ns * 32 + lane];
                eb0 = __ldg(&g_ebp[(size_t)(i + 2) * HH + h]);
            }
            ATTN_BODY(kv, vv, ebv);
        }
        i++;
        if (i >= r1) break;
        {
            float4 kv = kvb1, vv = vvb1; float ebv = eb1;
            if (i + 2 < r1) {
                const int ns = g_esrc[i + 2];
                kvb1 = ((const float4*)g_kd)[(size_t)ns * 32 + lane];
                vvb1 = ((const float4*)g_vd)[(size_t)ns * 32 + lane];
                eb1 = __ldg(&g_ebp[(size_t)(i + 2) * HH + h]);
            }
            ATTN_BODY(kv, vv, ebv);
        }
        i++;
    }
#undef ATTN_BODY

    const float inv = (den > 0.f) ? (1.f / den) : 0.f;
    acc.x *= inv; acc.y *= inv; acc.z *= inv; acc.w *= inv;
    ((float4*)g_agg)[(size_t)n * 32 + lane] = acc;
}

// ---------------- WMMA bf16-split GEMM core (templated tile height BM) ----------------
#define LDS_AB 72
#define LDS_C 132

template <int BM>
struct TCLayout {
    static constexpr int A_BYTES = BM * LDS_AB * 2;
    static constexpr int B_BYTES = 128 * LDS_AB * 2;
    static constexpr int OFF_AH = 0;
    static constexpr int OFF_AL = A_BYTES;
    static constexpr int OFF_BH = 2 * A_BYTES;
    static constexpr int OFF_BL = 2 * A_BYTES + B_BYTES;
    static constexpr int SMEM = 2 * A_BYTES + 2 * B_BYTES;
};
#define SMEM_TC128 (TCLayout<128>::SMEM)   // 73728
#define SMEM_TC64  (TCLayout<64>::SMEM)    // 55296

template <int BM>
__device__ __forceinline__ void cvt_storeA(char* smem, int row, int c4, float4 v) {
    __nv_bfloat162 h0 = __floats2bfloat162_rn(v.x, v.y);
    __nv_bfloat162 h1 = __floats2bfloat162_rn(v.z, v.w);
    float2 f0 = __bfloat1622float2(h0);
    float2 f1 = __bfloat1622float2(h1);
    __nv_bfloat162 l0 = __floats2bfloat162_rn(v.x - f0.x, v.y - f0.y);
    __nv_bfloat162 l1 = __floats2bfloat162_rn(v.z - f1.x, v.w - f1.y);
    uint2 ph, pl;
    ph.x = *(uint32_t*)&h0; ph.y = *(uint32_t*)&h1;
    pl.x = *(uint32_t*)&l0; pl.y = *(uint32_t*)&l1;
    *(uint2*)(smem + TCLayout<BM>::OFF_AH + ((size_t)row * LDS_AB + c4) * 2) = ph;
    *(uint2*)(smem + TCLayout<BM>::OFF_AL + ((size_t)row * LDS_AB + c4) * 2) = pl;
}

template <int BM, bool RELU, bool BIAS, bool RES, bool BNIN, bool RESBN, bool STATS>
__device__ __forceinline__ void gemm_core(
    const float* __restrict__ X,
    const __nv_bfloat16* __restrict__ WH, const __nv_bfloat16* __restrict__ WL,
    const float* __restrict__ bias, const float* __restrict__ res,
    const float* __restrict__ coefA, const float* __restrict__ coefR,
    float* __restrict__ stats, float* __restrict__ Y,
    int M, int K, int Co, int bm, int bn, char* smem) {
    constexpr int RF = BM / 64;          // 16-row frags per warp (2 or 1)
    const int tid = threadIdx.x;
    const int warp = tid >> 5;
    const int wm = (warp & 3) * (BM / 4);
    const int wn = (warp >> 2) * 64;
    const uint32_t sb = (uint32_t)__cvta_generic_to_shared(smem);

    wmma::fragment<wmma::accumulator, 16, 16, 16, float> acc[RF][4];
#pragma unroll
    for (int i = 0; i < RF; i++)
#pragma unroll
        for (int j = 0; j < 4; j++)
            wmma::fill_fragment(acc[i][j], 0.f);

    const __nv_bfloat16* sAh = (const __nv_bfloat16*)(smem + TCLayout<BM>::OFF_AH);
    const __nv_bfloat16* sAl = (const __nv_bfloat16*)(smem + TCLayout<BM>::OFF_AL);
    const __nv_bfloat16* sBh = (const __nv_bfloat16*)(smem + TCLayout<BM>::OFF_BH);
    const __nv_bfloat16* sBl = (const __nv_bfloat16*)(smem + TCLayout<BM>::OFF_BL);

    const int nch = K >> 6;
    for (int ch = 0; ch < nch; ch++) {
        const int kc0 = ch << 6;
        __syncthreads();
        // B: async copy of preconverted bf16 hi/lo
#pragma unroll
        for (int it = 0; it < 4; it++) {
            const int idx = tid + it * 256;
            const int row = idx >> 3;
            const int c8 = (idx & 7) << 3;
            const size_t g = (size_t)(bn + row) * K + kc0 + c8;
            const uint32_t so = sb + TCLayout<BM>::OFF_BH + (uint32_t)(row * LDS_AB + c8) * 2;
            cp_async16(so, WH + g);
            cp_async16(so + (TCLayout<BM>::OFF_BL - TCLayout<BM>::OFF_BH), WL + g);
        }
        CP_COMMIT();
        // A: convert BMx64 fp32 -> bf16 hi/lo
#pragma unroll
        for (int it = 0; it < BM / 16; it++) {
            const int idx = tid + it * 256;
            const int row = idx >> 4;
            const int c4 = (idx & 15) << 2;
            const int r = min(bm + row, M - 1);
            float4 v = *(const float4*)(X + (size_t)r * K + kc0 + c4);
            if (BNIN) {
                const int c = kc0 + c4;
                float4 s4 = *(const float4*)(coefA + c);
                float4 t4 = *(const float4*)(coefA + 128 + c);
                v.x = v.x * s4.x + t4.x; v.y = v.y * s4.y + t4.y;
                v.z = v.z * s4.z + t4.z; v.w = v.w * s4.w + t4.w;
            }
            cvt_storeA<BM>(smem, row, c4, v);
        }
        CP_WAIT0();
        __syncthreads();

#pragma unroll
        for (int ks = 0; ks < 4; ks++) {
            const int k0 = ks * 16;
            wmma::fragment<wmma::matrix_a, 16, 16, 16, __nv_bfloat16, wmma::row_major> ah[RF], al[RF];
#pragma unroll
            for (int i = 0; i < RF; i++) {
                wmma::load_matrix_sync(ah[i], sAh + (size_t)(wm + 16 * i) * LDS_AB + k0, LDS_AB);
                wmma::load_matrix_sync(al[i], sAl + (size_t)(wm + 16 * i) * LDS_AB + k0, LDS_AB);
            }
#pragma unroll
            for (int j = 0; j < 4; j++) {
                wmma::fragment<wmma::matrix_b, 16, 16, 16, __nv_bfloat16, wmma::col_major> bh, bl;
                wmma::load_matrix_sync(bh, sBh + (size_t)(wn + 16 * j) * LDS_AB + k0, LDS_AB);
                wmma::load_matrix_sync(bl, sBl + (size_t)(wn + 16 * j) * LDS_AB + k0, LDS_AB);
#pragma unroll
                for (int i = 0; i < RF; i++) {
                    wmma::mma_sync(acc[i][j], ah[i], bh, acc[i][j]);
                    wmma::mma_sync(acc[i][j], ah[i], bl, acc[i][j]);
                    wmma::mma_sync(acc[i][j], al[i], bh, acc[i][j]);
                }
            }
        }
    }

    // epilogue
    __syncthreads();
    float* sC = (float*)smem;
#pragma unroll
    for (int i = 0; i < RF; i++)
#pragma unroll
        for (int j = 0; j < 4; j++)
            wmma::store_matrix_sync(sC + (size_t)(wm + 16 * i) * LDS_C + wn + 16 * j,
                                    acc[i][j], LDS_C, wmma::mem_row_major);
    __syncthreads();

    float st_s[4] = {0.f, 0.f, 0.f, 0.f};
    float st_q[4] = {0.f, 0.f, 0.f, 0.f};
#pragma unroll
    for (int it = 0; it < BM / 8; it++) {
        const int idx = tid + it * 256;
        const int row = idx >> 5;
        const int c = (idx & 31) << 2;
        const int m = bm + row;
        if (m < M) {
            const int n = bn + c;
            float4 o = *(const float4*)(sC + (size_t)row * LDS_C + c);
            if (BIAS) {
                float4 b4 = *(const float4*)&bias[n];
                o.x += b4.x; o.y += b4.y; o.z += b4.z; o.w += b4.w;
            }
            if (RELU) {
                o.x = fmaxf(o.x, 0.f); o.y = fmaxf(o.y, 0.f);
                o.z = fmaxf(o.z, 0.f); o.w = fmaxf(o.w, 0.f);
            }
            if (RES) {
                float4 r4 = *(const float4*)&res[(size_t)m * Co + n];
                if (RESBN) {
                    float4 s4 = *(const float4*)(coefR + c);
                    float4 t4 = *(const float4*)(coefR + 128 + c);
                    r4.x = r4.x * s4.x + t4.x; r4.y = r4.y * s4.y + t4.y;
                    r4.z = r4.z * s4.z + t4.z; r4.w = r4.w * s4.w + t4.w;
                }
                o.x += r4.x; o.y += r4.y; o.z += r4.z; o.w += r4.w;
            }
            *(float4*)&Y[(size_t)m * Co + n] = o;
            if (STATS) {
                st_s[0] += o.x; st_s[1] += o.y; st_s[2] += o.z; st_s[3] += o.w;
                st_q[0] += o.x * o.x; st_q[1] += o.y * o.y;
                st_q[2] += o.z * o.z; st_q[3] += o.w * o.w;
            }
        }
    }
    if (STATS) {
        __syncthreads();
        float* sP = (float*)smem;
#pragma unroll
        for (int j = 0; j < 4; j++) { sP[tid * 8 + j] = st_s[j]; sP[tid * 8 + 4 + j] = st_q[j]; }
        __syncthreads();
        if (tid < 128) {
            const int cg = tid >> 2, sub = tid & 3;
            float s = 0.f, qq = 0.f;
#pragma unroll
            for (int rg = 0; rg < 8; rg++) {
                const int tt = rg * 32 + cg;
                s += sP[tt * 8 + sub];
                qq += sP[tt * 8 + 4 + sub];
            }
            atomicAdd(&stats[bn + tid], s);
            atomicAdd(&stats[128 + bn + tid], qq);
        }
    }
}

template <bool RELU, bool BIAS, bool RES, bool BNIN, bool RESBN, bool STATS>
__global__ void __launch_bounds__(256, 2)
tc_gemm_kernel(const float* __restrict__ X,
               const __nv_bfloat16* __restrict__ WH, const __nv_bfloat16* __restrict__ WL,
               const float* __restrict__ bias, const float* __restrict__ res,
               const float* __restrict__ coefA, const float* __restrict__ coefR,
               float* __restrict__ stats, float* __restrict__ Y, int M, int K, int Co) {
    extern __shared__ char smem[];
    gemm_core<128, RELU, BIAS, RES, BNIN, RESBN, STATS>(
        X, WH, WL, bias, res, coefA, coefR, stats, Y, M, K, Co,
        blockIdx.x * 128, blockIdx.y * 128, smem);
}

template <bool RELU, bool BIAS, bool RES, bool BNIN, bool RESBN, bool STATS>
__global__ void __launch_bounds__(256, 3)
tc_gemm64_kernel(const float* __restrict__ X,
                 const __nv_bfloat16* __restrict__ WH, const __nv_bfloat16* __restrict__ WL,
                 const float* __restrict__ bias, const float* __restrict__ res,
                 const float* __restrict__ coefA, const float* __restrict__ coefR,
                 float* __restrict__ stats, float* __restrict__ Y, int M, int K, int Co) {
    extern __shared__ char smem[];
    gemm_core<64, RELU, BIAS, RES, BNIN, RESBN, STATS>(
        X, WH, WL, bias, res, coefA, coefR, stats, Y, M, K, Co,
        blockIdx.x * 64, blockIdx.y * 128, smem);
}

__global__ void __launch_bounds__(256, 2)
qkv_gemm_kernel(const float* __restrict__ q, const float* __restrict__ k,
                const float* __restrict__ v) {
    extern __shared__ char smem[];
    const int z = blockIdx.z;
    const float* X = (z == 0) ? q : (z == 1) ? k : v;
    float* Y = (z == 0) ? g_qd : (z == 1) ? g_kd : g_vd;
    gemm_core<128, false, false, false, false, false, false>(
        X, g_wh + z * 16384, g_wl + z * 16384,
        nullptr, nullptr, nullptr, nullptr, nullptr, Y, NN, CD, CD,
        blockIdx.x * 128, 0, smem);
}

// ---------------- edge bias + dst histogram (fused) ----------------
__global__ void __launch_bounds__(256)
eb_kernel(const float* __restrict__ ef, const float* __restrict__ We,
          const float* __restrict__ be, const int* __restrict__ dst) {
    __shared__ float sWe[HH * EDD];
    __shared__ float sbe[HH];
    for (int i = threadIdx.x; i < HH * EDD; i += 256) sWe[i] = We[i];
    if (threadIdx.x < HH) sbe[threadIdx.x] = be[threadIdx.x];
    __syncthreads();

    const int e = blockIdx.x * 256 + threadIdx.x;
    atomicAdd(&g_cnt[dst[e]], 1);
    const float4* efp = (const float4*)(ef + (size_t)e * EDD);
    float acc[HH];
#pragma unroll
    for (int h = 0; h < HH; h++) acc[h] = sbe[h];
#pragma unroll
    for (int j4 = 0; j4 < EDD / 4; j4++) {
        float4 v = efp[j4];
#pragma unroll
        for (int h = 0; h < HH; h++) {
            float4 w = *(const float4*)&sWe[h * EDD + j4 * 4];
            acc[h] += v.x * w.x + v.y * w.y + v.z * w.z + v.w * w.w;
        }
    }
    float4 o0 = make_float4(acc[0], acc[1], acc[2], acc[3]);
    float4 o1 = make_float4(acc[4], acc[5], acc[6], acc[7]);
    ((float4*)g_eb)[(size_t)e * 2 + 0] = o0;
    ((float4*)g_eb)[(size_t)e * 2 + 1] = o1;
}

// ---------------- BN coefficients ----------------
__global__ void bn_coef_kernel(const float* __restrict__ sums,
                               const float* __restrict__ g, const float* __restrict__ b,
                               float* __restrict__ coef) {
    const int c = threadIdx.x;
    const float inv = 1.f / (float)NN;
    const float mu = sums[c] * inv;
    const float var = sums[128 + c] * inv - mu * mu;
    const float rs = rsqrtf(var + EPS);
    const float sc = rs * g[c];
    coef[c] = sc;
    coef[128 + c] = b[c] - mu * sc;
}

// ---------------- final apply ----------------
__global__ void __launch_bounds__(256)
bn_apply_kernel(const float* __restrict__ X, float* __restrict__ Y,
                const float* __restrict__ coef) {
    const int i = blockIdx.x * 256 + threadIdx.x;
    const int c = i & (CD - 1);
    Y[i] = X[i] * coef[c] + coef[128 + c];
}

// ---------------- launcher ----------------
extern "C" void kernel_launch(void* const* d_in, const int* in_sizes, int n_in,
                              void* d_out, int out_size) {
    const float* q   = (const float*)d_in[0];
    const float* k   = (const float*)d_in[1];
    const float* v   = (const float*)d_in[2];
    const float* ef  = (const float*)d_in[3];
    const int*   src = (const int*)d_in[4];
    const int*   dst = (const int*)d_in[5];
    const float* Wq  = (const float*)d_in[6];
    const float* Wk  = (const float*)d_in[7];
    const float* Wv  = (const float*)d_in[8];
    const float* We  = (const float*)d_in[9];
    const float* be  = (const float*)d_in[10];
    const float* Wo  = (const float*)d_in[11];
    const float* W1  = (const float*)d_in[12];
    const float* b1  = (const float*)d_in[13];
    const float* W2  = (const float*)d_in[14];
    const float* b2  = (const float*)d_in[15];
    const float* g1  = (const float*)d_in[16];
    const float* bt1 = (const float*)d_in[17];
    const float* g2  = (const float*)d_in[18];
    const float* bt2 = (const float*)d_in[19];
    float* out = (float*)d_out;

    float* p_agg; cudaGetSymbolAddress((void**)&p_agg, g_agg);
    float* p_rst; cudaGetSymbolAddress((void**)&p_rst, g_rst);
    float* p_h1; cudaGetSymbolAddress((void**)&p_h1, g_h1);
    float* p_h2; cudaGetSymbolAddress((void**)&p_h2, g_h2);
    float* p_stats; cudaGetSymbolAddress((void**)&p_stats, g_stats);
    float* p_coef; cudaGetSymbolAddress((void**)&p_coef, g_coef);
    __nv_bfloat16* p_wh; cudaGetSymbolAddress((void**)&p_wh, g_wh);
    __nv_bfloat16* p_wl; cudaGetSymbolAddress((void**)&p_wl, g_wl);

    static cudaStream_t s2 = nullptr;
    static cudaEvent_t evF = nullptr, evJ = nullptr;
    if (!s2) {
        cudaStreamCreateWithFlags(&s2, cudaStreamNonBlocking);
        cudaEventCreateWithFlags(&evF, cudaEventDisableTiming);
        cudaEventCreateWithFlags(&evJ, cudaEventDisableTiming);
    }

    cudaFuncSetAttribute(qkv_gemm_kernel, cudaFuncAttributeMaxDynamicSharedMemorySize, SMEM_TC128);
    cudaFuncSetAttribute(tc_gemm64_kernel<false, false, true,  false, false, true >, cudaFuncAttributeMaxDynamicSharedMemorySize, SMEM_TC64);
    cudaFuncSetAttribute(tc_gemm_kernel<true,  true,  false, true,  false, false>, cudaFuncAttributeMaxDynamicSharedMemorySize, SMEM_TC128);
    cudaFuncSetAttribute(tc_gemm64_kernel<false, true,  true,  false, true,  true >, cudaFuncAttributeMaxDynamicSharedMemorySize, SMEM_TC64);

    // fork at t0: edge preprocessing on s2 runs concurrently with initconv+qkv
    cudaEventRecord(evF, 0);
    cudaStreamWaitEvent(s2, evF, 0);

    zerocnt_kernel<<<NB, 256, 0, s2>>>();
    eb_kernel<<<EE / 256, 256, 0, s2>>>(ef, We, be, dst);
    scan1_kernel<<<NB, 256, 0, s2>>>();
    scan2_kernel<<<1, 256, 0, s2>>>();
    scan3_kernel<<<NB, 256, 0, s2>>>();
    scatter_kernel<<<EE / 256, 256, 0, s2>>>(src, dst);
    cudaEventRecord(evJ, s2);

    initconv_kernel<<<WTOT / 256, 256>>>(Wq, Wk, Wv, Wo, W1, W2);

    const dim3 gQKV(313, 1, 3);
    const dim3 g64(625, 1);
    const dim3 gH(313, 2);

    qkv_gemm_kernel<<<gQKV, 256, SMEM_TC128>>>(q, k, v);

    cudaStreamWaitEvent(0, evJ, 0);
    attn_kernel<<<NN / 8, 256>>>();

    // out proj + residual, stats for BN1 fused (BM=64: 625 CTAs, no tail rows)
    tc_gemm64_kernel<false, false, true, false, false, true><<<g64, 256, SMEM_TC64>>>(
        p_agg, p_wh + WOFF_O, p_wl + WOFF_O, nullptr, q, nullptr, nullptr, p_stats, p_rst, NN, CD, CD);
    bn_coef_kernel<<<1, 128>>>(p_stats, g1, bt1, p_coef);

    // FFN
    tc_gemm_kernel<true, true, false, true, false, false><<<gH, 256, SMEM_TC128>>>(
        p_rst, p_wh + WOFF_1, p_wl + WOFF_1, b1, nullptr, p_coef, nullptr, nullptr, p_h1, NN, CD, C2);
    tc_gemm64_kernel<false, true, true, false, true, true><<<g64, 256, SMEM_TC64>>>(
        p_h1, p_wh + WOFF_2, p_wl + WOFF_2, b2, p_rst, nullptr, p_coef, p_stats + 2 * CD, p_h2, NN, C2, CD);
    bn_coef_kernel<<<1, 128>>>(p_stats + 2 * CD, g2, bt2, p_coef + 2 * CD);
    bn_apply_kernel<<<NN * CD / 256, 256>>>(p_h2, out, p_coef + 2 * CD);
}